// round 1
// baseline (speedup 1.0000x reference)
#include <cuda_runtime.h>
#include <cuda_bf16.h>
#include <cstdio>

// Problem constants
#define BB 4
#define TT 2048
#define CC 1024
#define HH 16
#define HD 64
#define MTOK (BB*TT)        // 8192
#define C3  (3*CC)          // 3072

// Scratch (allocation-guard-safe: __device__ globals)
__device__ float g_qkv[(size_t)MTOK * C3];   // 96 MB
__device__ float g_att[(size_t)MTOK * CC];   // 32 MB

// ---------------------------------------------------------------------------
// SGEMM: Out[m][n] = sum_k A[m][k] * W[n][k] + bias[n]
// A: MxK row-major, W: NxK row-major (torch Linear weight), both K-contiguous.
// BM=BN=128, BK=16, 256 threads, 8x8 microtile, register prefetch.
// ---------------------------------------------------------------------------
__global__ void __launch_bounds__(256, 2)
sgemm_nt_bias(const float* __restrict__ A, const float* __restrict__ W,
              const float* __restrict__ bias, float* __restrict__ Out,
              int M, int N, int K)
{
    __shared__ float As[16][132];
    __shared__ float Bs[16][132];

    const int tid = threadIdx.x;
    const int m0 = blockIdx.y * 128;
    const int n0 = blockIdx.x * 128;
    const int tr = tid >> 4;        // 0..15
    const int tc = tid & 15;        // 0..15

    const int lr = tid >> 2;        // 0..63
    const int lk = (tid & 3) << 2;  // 0,4,8,12

    const float* Aptr = A + (size_t)(m0 + lr) * K + lk;
    const float* Wptr = W + (size_t)(n0 + lr) * K + lk;

    float acc[8][8] = {};
    float4 ra[2], rb[2];

    const int nk = K >> 4;
    ra[0] = *(const float4*)(Aptr);
    ra[1] = *(const float4*)(Aptr + (size_t)64 * K);
    rb[0] = *(const float4*)(Wptr);
    rb[1] = *(const float4*)(Wptr + (size_t)64 * K);

    for (int kb = 0; kb < nk; kb++) {
        #pragma unroll
        for (int hh = 0; hh < 2; hh++) {
            int row = lr + 64 * hh;
            As[lk + 0][row] = ra[hh].x; As[lk + 1][row] = ra[hh].y;
            As[lk + 2][row] = ra[hh].z; As[lk + 3][row] = ra[hh].w;
            Bs[lk + 0][row] = rb[hh].x; Bs[lk + 1][row] = rb[hh].y;
            Bs[lk + 2][row] = rb[hh].z; Bs[lk + 3][row] = rb[hh].w;
        }
        __syncthreads();
        if (kb + 1 < nk) {
            const float* An = Aptr + (size_t)(kb + 1) * 16;
            const float* Wn = Wptr + (size_t)(kb + 1) * 16;
            ra[0] = *(const float4*)(An);
            ra[1] = *(const float4*)(An + (size_t)64 * K);
            rb[0] = *(const float4*)(Wn);
            rb[1] = *(const float4*)(Wn + (size_t)64 * K);
        }
        #pragma unroll
        for (int k = 0; k < 16; k++) {
            float fa[8], fb[8];
            *(float4*)&fa[0] = *(const float4*)&As[k][tr * 8];
            *(float4*)&fa[4] = *(const float4*)&As[k][tr * 8 + 4];
            *(float4*)&fb[0] = *(const float4*)&Bs[k][tc * 8];
            *(float4*)&fb[4] = *(const float4*)&Bs[k][tc * 8 + 4];
            #pragma unroll
            for (int i = 0; i < 8; i++)
                #pragma unroll
                for (int j = 0; j < 8; j++)
                    acc[i][j] = fmaf(fa[i], fb[j], acc[i][j]);
        }
        __syncthreads();
    }

    #pragma unroll
    for (int i = 0; i < 8; i++) {
        int m = m0 + tr * 8 + i;
        #pragma unroll
        for (int j = 0; j < 8; j += 4) {
            int n = n0 + tc * 8 + j;
            float4 o;
            o.x = acc[i][j + 0] + bias[n + 0];
            o.y = acc[i][j + 1] + bias[n + 1];
            o.z = acc[i][j + 2] + bias[n + 2];
            o.w = acc[i][j + 3] + bias[n + 3];
            *(float4*)&Out[(size_t)m * N + n] = o;
        }
    }
}

// ---------------------------------------------------------------------------
// Flash attention (causal), fp32.
// Grid: (T/64, H, B), 256 threads.
// Q/K tiles stored d-major ([d][r]) with 16B-chunk XOR swizzle for
// conflict-free LDS.128 in the S phase. V and S (=P) stored plain.
// Thread microtiles: rows r0..r0+3 (rg=tid/16), cols/d d0..d0+3 (cg=tid%16).
// Online softmax: row stats in smem, 16-lane shuffle reductions.
// ---------------------------------------------------------------------------
__global__ void __launch_bounds__(256)
attn_kernel(const float* __restrict__ qkv, float* __restrict__ out)
{
    extern __shared__ float sm[];
    float* Qs = sm;              // 64*64 (d-major, swizzled)
    float* Ks = sm + 4096;       // 64*64 (d-major, swizzled)
    float* Vs = sm + 8192;       // 64*64 (k-major, plain)
    float* Ss = sm + 12288;      // 64*64 (r-major, plain)
    float* m_s = sm + 16384;     // 64
    float* l_s = m_s + 64;       // 64
    float* f_s = l_s + 64;       // 64

    const int tid = threadIdx.x;
    const int qt = blockIdx.x;          // q tile 0..31
    const int h  = blockIdx.y;
    const int b  = blockIdx.z;
    const int t0 = qt * 64;

    const int rg = tid >> 4;            // 0..15
    const int cg = tid & 15;            // 0..15
    const int r0 = rg << 2;
    const int c0 = cg << 2;

    const float scale = 0.125f;         // 1/sqrt(64)

    if (tid < 64) { m_s[tid] = -1e30f; l_s[tid] = 0.0f; }

    // Load Q tile: gmem row (t0+r), 64 contiguous d floats; store transposed+swizzled.
    #pragma unroll
    for (int it = 0; it < 4; it++) {
        int f = tid + 256 * it;
        int r = f >> 4, dq = f & 15;
        const float4 v = *(const float4*)&qkv[(size_t)(b * TT + t0 + r) * C3 + h * HD + 4 * dq];
        int cr = r >> 2, off = r & 3;
        float vv[4] = {v.x, v.y, v.z, v.w};
        #pragma unroll
        for (int u = 0; u < 4; u++) {
            int d = 4 * dq + u;
            Qs[d * 64 + ((cr ^ (d & 15)) << 2) + off] = vv[u];
        }
    }
    __syncthreads();

    float acc[4][4] = {};

    for (int kt = 0; kt <= qt; kt++) {
        // Load K (transposed+swizzled) and V (plain) tiles.
        #pragma unroll
        for (int it = 0; it < 4; it++) {
            int f = tid + 256 * it;
            int r = f >> 4, dq = f & 15;
            size_t gi = (size_t)(b * TT + kt * 64 + r) * C3 + h * HD + 4 * dq;
            float4 kv = *(const float4*)&qkv[gi + CC];
            float4 vv = *(const float4*)&qkv[gi + 2 * CC];
            int cr = r >> 2, off = r & 3;
            float ka[4] = {kv.x, kv.y, kv.z, kv.w};
            #pragma unroll
            for (int u = 0; u < 4; u++) {
                int d = 4 * dq + u;
                Ks[d * 64 + ((cr ^ (d & 15)) << 2) + off] = ka[u];
            }
            *(float4*)&Vs[r * 64 + 4 * dq] = vv;
        }
        __syncthreads();

        // S = Q K^T (4x4 microtile per thread)
        float s[4][4] = {};
        #pragma unroll 8
        for (int d = 0; d < 64; d++) {
            int sw = d & 15;
            float4 q4 = *(const float4*)&Qs[d * 64 + ((rg ^ sw) << 2)];
            float4 k4 = *(const float4*)&Ks[d * 64 + ((cg ^ sw) << 2)];
            float qa[4] = {q4.x, q4.y, q4.z, q4.w};
            float kk[4] = {k4.x, k4.y, k4.z, k4.w};
            #pragma unroll
            for (int i = 0; i < 4; i++)
                #pragma unroll
                for (int j = 0; j < 4; j++)
                    s[i][j] = fmaf(qa[i], kk[j], s[i][j]);
        }

        const bool diag = (kt == qt);
        #pragma unroll
        for (int i = 0; i < 4; i++)
            #pragma unroll
            for (int j = 0; j < 4; j++) {
                s[i][j] *= scale;
                if (diag && (c0 + j > r0 + i)) s[i][j] = -1e30f;
            }

        // Online softmax per row (16-lane reductions, lanes stay in 16-groups).
        #pragma unroll
        for (int i = 0; i < 4; i++) {
            float mloc = fmaxf(fmaxf(s[i][0], s[i][1]), fmaxf(s[i][2], s[i][3]));
            #pragma unroll
            for (int off = 8; off > 0; off >>= 1)
                mloc = fmaxf(mloc, __shfl_xor_sync(0xffffffffu, mloc, off));
            float mprev = m_s[r0 + i];
            float mnew = fmaxf(mprev, mloc);
            float p[4], lsum;
            p[0] = __expf(s[i][0] - mnew);
            p[1] = __expf(s[i][1] - mnew);
            p[2] = __expf(s[i][2] - mnew);
            p[3] = __expf(s[i][3] - mnew);
            lsum = (p[0] + p[1]) + (p[2] + p[3]);
            #pragma unroll
            for (int off = 8; off > 0; off >>= 1)
                lsum += __shfl_xor_sync(0xffffffffu, lsum, off);
            if (cg == 0) {
                float fct = __expf(mprev - mnew);
                l_s[r0 + i] = l_s[r0 + i] * fct + lsum;
                m_s[r0 + i] = mnew;
                f_s[r0 + i] = fct;
            }
            *(float4*)&Ss[(r0 + i) * 64 + c0] = make_float4(p[0], p[1], p[2], p[3]);
        }
        __syncthreads();

        // O += P V  (rescale acc by row factor first)
        #pragma unroll
        for (int i = 0; i < 4; i++) {
            float fct = f_s[r0 + i];
            #pragma unroll
            for (int j = 0; j < 4; j++) acc[i][j] *= fct;
        }
        #pragma unroll 4
        for (int k = 0; k < 64; k++) {
            float4 v4 = *(const float4*)&Vs[k * 64 + c0];
            float vb[4] = {v4.x, v4.y, v4.z, v4.w};
            #pragma unroll
            for (int i = 0; i < 4; i++) {
                float p = Ss[(r0 + i) * 64 + k];
                #pragma unroll
                for (int j = 0; j < 4; j++)
                    acc[i][j] = fmaf(p, vb[j], acc[i][j]);
            }
        }
        __syncthreads();
    }

    // Normalize and write to g_att in (B,T,C) layout.
    #pragma unroll
    for (int i = 0; i < 4; i++) {
        float inv = 1.0f / l_s[r0 + i];
        float4 o = make_float4(acc[i][0] * inv, acc[i][1] * inv,
                               acc[i][2] * inv, acc[i][3] * inv);
        *(float4*)&out[(size_t)(b * TT + t0 + r0 + i) * CC + h * HD + c0] = o;
    }
}

// ---------------------------------------------------------------------------
// Launch
// ---------------------------------------------------------------------------
extern "C" void kernel_launch(void* const* d_in, const int* in_sizes, int n_in,
                              void* d_out, int out_size)
{
    const float* x      = (const float*)d_in[0];
    const float* qkv_w  = (const float*)d_in[1];
    const float* qkv_b  = (const float*)d_in[2];
    const float* out_w  = (const float*)d_in[3];
    const float* out_b  = (const float*)d_in[4];
    float* out = (float*)d_out;

    float* qkv_buf = nullptr;
    float* att_buf = nullptr;
    cudaGetSymbolAddress((void**)&qkv_buf, g_qkv);
    cudaGetSymbolAddress((void**)&att_buf, g_att);

    // Opt into 66 KB dynamic smem for the attention kernel (idempotent, no alloc).
    const int attn_smem = (4 * 4096 + 3 * 64) * (int)sizeof(float);  // 66304 B
    cudaFuncSetAttribute(attn_kernel, cudaFuncAttributeMaxDynamicSharedMemorySize, attn_smem);

    // 1) QKV projection: (8192 x 1024) @ (3072 x 1024)^T + b
    {
        dim3 grid(C3 / 128, MTOK / 128);
        sgemm_nt_bias<<<grid, 256>>>(x, qkv_w, qkv_b, qkv_buf, MTOK, C3, CC);
    }
    // 2) Causal flash attention
    {
        dim3 grid(TT / 64, HH, BB);
        attn_kernel<<<grid, 256, attn_smem>>>(qkv_buf, att_buf);
    }
    // 3) Output projection: (8192 x 1024) @ (1024 x 1024)^T + b
    {
        dim3 grid(CC / 128, MTOK / 128);
        sgemm_nt_bias<<<grid, 256>>>(att_buf, out_w, out_b, out, MTOK, CC, CC);
    }
}

// round 3
// speedup vs baseline: 1.3828x; 1.3828x over previous
#include <cuda_runtime.h>
#include <cuda_bf16.h>
#include <cstdint>

// Problem constants
#define BB 4
#define TT 2048
#define CC 1024
#define HH 16
#define HD 64
#define MTOK (BB*TT)        // 8192
#define C3  (3*CC)          // 3072

// Scratch (allocation-guard-safe: __device__ globals). bf16 pairs stored as u32.
__device__ float    g_qkv[(size_t)MTOK * C3];            // 96 MB fp32
__device__ uint32_t g_xh[(size_t)MTOK * CC / 2],  g_xl[(size_t)MTOK * CC / 2];
__device__ uint32_t g_w1h[(size_t)C3 * CC / 2],   g_w1l[(size_t)C3 * CC / 2];
__device__ uint32_t g_w2h[(size_t)CC * CC / 2],   g_w2l[(size_t)CC * CC / 2];
__device__ uint32_t g_ath[(size_t)MTOK * CC / 2], g_atl[(size_t)MTOK * CC / 2];

// ---------------------------------------------------------------------------
// Helpers (target-portable: mma.sync / ldmatrix / cp.async only)
// ---------------------------------------------------------------------------
__device__ __forceinline__ uint32_t smem_u32(const void* p) {
    uint32_t a;
    asm("{ .reg .u64 t; cvta.to.shared.u64 t, %1; cvt.u32.u64 %0, t; }" : "=r"(a) : "l"(p));
    return a;
}
// pack (x,y) -> bf16x2 with x in LOW half
__device__ __forceinline__ uint32_t bf16x2_of(float lo, float hi) {
    uint32_t r;
    asm("cvt.rn.bf16x2.f32 %0, %1, %2;" : "=r"(r) : "f"(hi), "f"(lo));
    return r;
}
__device__ __forceinline__ void cp16(uint32_t s, const void* g) {
    asm volatile("cp.async.cg.shared.global [%0], [%1], 16;" :: "r"(s), "l"(g) : "memory");
}
__device__ __forceinline__ void ldsm4(uint32_t* r, uint32_t a) {
    asm volatile("ldmatrix.sync.aligned.m8n8.x4.shared.b16 {%0,%1,%2,%3}, [%4];"
        : "=r"(r[0]), "=r"(r[1]), "=r"(r[2]), "=r"(r[3]) : "r"(a));
}
__device__ __forceinline__ void mma16816(float* c, const uint32_t* a, const uint32_t* b) {
    asm volatile("mma.sync.aligned.m16n8k16.row.col.f32.bf16.bf16.f32 "
        "{%0,%1,%2,%3}, {%4,%5,%6,%7}, {%8,%9}, {%0,%1,%2,%3};"
        : "+f"(c[0]), "+f"(c[1]), "+f"(c[2]), "+f"(c[3])
        : "r"(a[0]), "r"(a[1]), "r"(a[2]), "r"(a[3]), "r"(b[0]), "r"(b[1]));
}

// ---------------------------------------------------------------------------
// fp32 -> bf16 hi/lo split (elementwise)
// ---------------------------------------------------------------------------
__global__ void split_bf16(const float4* __restrict__ in, uint32_t* __restrict__ hi,
                           uint32_t* __restrict__ lo, int n4)
{
    int i = blockIdx.x * blockDim.x + threadIdx.x;
    if (i >= n4) return;
    float4 f = in[i];
    uint32_t h01 = bf16x2_of(f.x, f.y);
    uint32_t h23 = bf16x2_of(f.z, f.w);
    float r0 = f.x - __uint_as_float(h01 << 16);
    float r1 = f.y - __uint_as_float(h01 & 0xffff0000u);
    float r2 = f.z - __uint_as_float(h23 << 16);
    float r3 = f.w - __uint_as_float(h23 & 0xffff0000u);
    *(uint2*)&hi[2 * i] = make_uint2(h01, h23);
    *(uint2*)&lo[2 * i] = make_uint2(bf16x2_of(r0, r1), bf16x2_of(r2, r3));
}

// ---------------------------------------------------------------------------
// Split-precision bf16 GEMM via mma.sync:
//   Out[m][n] = sum_k A[m][k]*W[n][k] + bias[n]
//   D = Ah*Bh + Ah*Bl + Al*Bh  (all tiles K-major bf16)
// 128x128x32 CTA tile, 8 warps (4 M x 2 N), 3-stage cp.async pipeline.
// smem per stage: 4 tiles x (128 rows x 64B) = 32 KB. XOR swizzle on 16B chunks.
// ---------------------------------------------------------------------------
#define BK 32
#define STAGES 3
#define SBYTES 32768
#define GEMM_DSM (STAGES * SBYTES + 1024)

__global__ void __launch_bounds__(256, 1)
gemm_mma(const uint32_t* __restrict__ Ah2, const uint32_t* __restrict__ Al2,
         const uint32_t* __restrict__ Bh2, const uint32_t* __restrict__ Bl2,
         const float* __restrict__ bias, float* __restrict__ Out,
         int M, int N, int K)
{
    extern __shared__ char dsm[];
    const uint32_t sbase = (smem_u32(dsm) + 1023u) & ~1023u;

    const int tid  = threadIdx.x;
    const int lane = tid & 31;
    const int warp = tid >> 5;
    const int wm = warp & 3;        // 0..3  (M)
    const int wn = warp >> 2;       // 0..1  (N)
    const int m0 = blockIdx.y * 128;
    const int n0 = blockIdx.x * 128;

    // loader mapping: row lr (0..127), 16B k-chunks lkc, lkc+1
    const int lr  = tid >> 1;
    const int lkc = (tid & 1) * 2;

    const char* pAh = (const char*)Ah2 + ((size_t)(m0 + lr) * K) * 2;
    const char* pAl = (const char*)Al2 + ((size_t)(m0 + lr) * K) * 2;
    const char* pBh = (const char*)Bh2 + ((size_t)(n0 + lr) * K) * 2;
    const char* pBl = (const char*)Bl2 + ((size_t)(n0 + lr) * K) * 2;
    const int rsw = (lr >> 1) & 3;   // row swizzle key

    float acc[2][8][4] = {};

    const int NKI = K / BK;

    auto load_stage = [&](int s, int it) {
        const uint32_t ss = sbase + s * SBYTES;
        const int gko = it * BK * 2;     // byte offset along K
        #pragma unroll
        for (int i = 0; i < 2; i++) {
            const int kc = lkc + i;
            const uint32_t so = (uint32_t)(lr * 64 + ((kc ^ rsw) << 4));
            const int go = gko + kc * 16;
            cp16(ss + so,          pAh + go);
            cp16(ss + 8192 + so,   pAl + go);
            cp16(ss + 16384 + so,  pBh + go);
            cp16(ss + 24576 + so,  pBl + go);
        }
    };

    auto compute_stage = [&](int s) {
        const uint32_t ss = sbase + s * SBYTES;
        #pragma unroll
        for (int ks = 0; ks < 2; ks++) {
            uint32_t ah[2][4], al[2][4];
            #pragma unroll
            for (int mt = 0; mt < 2; mt++) {
                int row = wm * 32 + mt * 16 + (lane & 15);
                int kc  = ks * 2 + (lane >> 4);
                uint32_t so = (uint32_t)(row * 64 + ((kc ^ ((row >> 1) & 3)) << 4));
                ldsm4(ah[mt], ss + so);
                ldsm4(al[mt], ss + 8192 + so);
            }
            uint32_t bh[4][4], bl[4][4];
            #pragma unroll
            for (int jj = 0; jj < 4; jj++) {
                int row = wn * 64 + jj * 16 + (lane & 7) + ((lane >> 4) << 3);
                int kc  = ks * 2 + ((lane >> 3) & 1);
                uint32_t so = (uint32_t)(row * 64 + ((kc ^ ((row >> 1) & 3)) << 4));
                ldsm4(bh[jj], ss + 16384 + so);
                ldsm4(bl[jj], ss + 24576 + so);
            }
            #pragma unroll
            for (int mt = 0; mt < 2; mt++)
                #pragma unroll
                for (int nt = 0; nt < 8; nt++) {
                    const uint32_t* bph = &bh[nt >> 1][(nt & 1) * 2];
                    const uint32_t* bpl = &bl[nt >> 1][(nt & 1) * 2];
                    mma16816(acc[mt][nt], ah[mt], bph);
                    mma16816(acc[mt][nt], ah[mt], bpl);
                    mma16816(acc[mt][nt], al[mt], bph);
                }
        }
    };

    #pragma unroll
    for (int s = 0; s < STAGES - 1; s++) {
        load_stage(s, s);
        asm volatile("cp.async.commit_group;" ::: "memory");
    }

    for (int it = 0; it < NKI; it++) {
        asm volatile("cp.async.wait_group %0;" :: "n"(STAGES - 2) : "memory");
        __syncthreads();
        const int nit = it + STAGES - 1;
        if (nit < NKI) load_stage(nit % STAGES, nit);
        asm volatile("cp.async.commit_group;" ::: "memory");
        compute_stage(it % STAGES);
    }

    // Epilogue: direct fragment stores + bias
    const int rr = lane >> 2;
    const int cc = (lane & 3) * 2;
    #pragma unroll
    for (int mt = 0; mt < 2; mt++)
        #pragma unroll
        for (int nt = 0; nt < 8; nt++) {
            const int col = n0 + wn * 64 + nt * 8 + cc;
            const float b0 = bias[col], b1 = bias[col + 1];
            #pragma unroll
            for (int hf = 0; hf < 2; hf++) {
                const int row = m0 + wm * 32 + mt * 16 + rr + hf * 8;
                float2 v = make_float2(acc[mt][nt][hf * 2 + 0] + b0,
                                       acc[mt][nt][hf * 2 + 1] + b1);
                *(float2*)&Out[(size_t)row * N + col] = v;
            }
        }
}

// ---------------------------------------------------------------------------
// Flash attention (causal), fp32 compute; outputs bf16 hi/lo split directly.
// ---------------------------------------------------------------------------
__global__ void __launch_bounds__(256)
attn_kernel(const float* __restrict__ qkv, uint32_t* __restrict__ oh,
            uint32_t* __restrict__ ol)
{
    extern __shared__ float sm[];
    float* Qs = sm;
    float* Ks = sm + 4096;
    float* Vs = sm + 8192;
    float* Ss = sm + 12288;
    float* m_s = sm + 16384;
    float* l_s = m_s + 64;
    float* f_s = l_s + 64;

    const int tid = threadIdx.x;
    const int qt = blockIdx.x;
    const int h  = blockIdx.y;
    const int b  = blockIdx.z;
    const int t0 = qt * 64;

    const int rg = tid >> 4;
    const int cg = tid & 15;
    const int r0 = rg << 2;
    const int c0 = cg << 2;

    const float scale = 0.125f;

    if (tid < 64) { m_s[tid] = -1e30f; l_s[tid] = 0.0f; }

    #pragma unroll
    for (int it = 0; it < 4; it++) {
        int f = tid + 256 * it;
        int r = f >> 4, dq = f & 15;
        const float4 v = *(const float4*)&qkv[(size_t)(b * TT + t0 + r) * C3 + h * HD + 4 * dq];
        int cr = r >> 2, off = r & 3;
        float vv[4] = {v.x, v.y, v.z, v.w};
        #pragma unroll
        for (int u = 0; u < 4; u++) {
            int d = 4 * dq + u;
            Qs[d * 64 + ((cr ^ (d & 15)) << 2) + off] = vv[u];
        }
    }
    __syncthreads();

    float acc[4][4] = {};

    for (int kt = 0; kt <= qt; kt++) {
        #pragma unroll
        for (int it = 0; it < 4; it++) {
            int f = tid + 256 * it;
            int r = f >> 4, dq = f & 15;
            size_t gi = (size_t)(b * TT + kt * 64 + r) * C3 + h * HD + 4 * dq;
            float4 kv = *(const float4*)&qkv[gi + CC];
            float4 vv = *(const float4*)&qkv[gi + 2 * CC];
            int cr = r >> 2, off = r & 3;
            float ka[4] = {kv.x, kv.y, kv.z, kv.w};
            #pragma unroll
            for (int u = 0; u < 4; u++) {
                int d = 4 * dq + u;
                Ks[d * 64 + ((cr ^ (d & 15)) << 2) + off] = ka[u];
            }
            *(float4*)&Vs[r * 64 + 4 * dq] = vv;
        }
        __syncthreads();

        float s[4][4] = {};
        #pragma unroll 8
        for (int d = 0; d < 64; d++) {
            int sw = d & 15;
            float4 q4 = *(const float4*)&Qs[d * 64 + ((rg ^ sw) << 2)];
            float4 k4 = *(const float4*)&Ks[d * 64 + ((cg ^ sw) << 2)];
            float qa[4] = {q4.x, q4.y, q4.z, q4.w};
            float kk[4] = {k4.x, k4.y, k4.z, k4.w};
            #pragma unroll
            for (int i = 0; i < 4; i++)
                #pragma unroll
                for (int j = 0; j < 4; j++)
                    s[i][j] = fmaf(qa[i], kk[j], s[i][j]);
        }

        const bool diag = (kt == qt);
        #pragma unroll
        for (int i = 0; i < 4; i++)
            #pragma unroll
            for (int j = 0; j < 4; j++) {
                s[i][j] *= scale;
                if (diag && (c0 + j > r0 + i)) s[i][j] = -1e30f;
            }

        #pragma unroll
        for (int i = 0; i < 4; i++) {
            float mloc = fmaxf(fmaxf(s[i][0], s[i][1]), fmaxf(s[i][2], s[i][3]));
            #pragma unroll
            for (int off = 8; off > 0; off >>= 1)
                mloc = fmaxf(mloc, __shfl_xor_sync(0xffffffffu, mloc, off));
            float mprev = m_s[r0 + i];
            float mnew = fmaxf(mprev, mloc);
            float p[4], lsum;
            p[0] = __expf(s[i][0] - mnew);
            p[1] = __expf(s[i][1] - mnew);
            p[2] = __expf(s[i][2] - mnew);
            p[3] = __expf(s[i][3] - mnew);
            lsum = (p[0] + p[1]) + (p[2] + p[3]);
            #pragma unroll
            for (int off = 8; off > 0; off >>= 1)
                lsum += __shfl_xor_sync(0xffffffffu, lsum, off);
            if (cg == 0) {
                float fct = __expf(mprev - mnew);
                l_s[r0 + i] = l_s[r0 + i] * fct + lsum;
                m_s[r0 + i] = mnew;
                f_s[r0 + i] = fct;
            }
            *(float4*)&Ss[(r0 + i) * 64 + c0] = make_float4(p[0], p[1], p[2], p[3]);
        }
        __syncthreads();

        #pragma unroll
        for (int i = 0; i < 4; i++) {
            float fct = f_s[r0 + i];
            #pragma unroll
            for (int j = 0; j < 4; j++) acc[i][j] *= fct;
        }
        #pragma unroll 4
        for (int k = 0; k < 64; k++) {
            float4 v4 = *(const float4*)&Vs[k * 64 + c0];
            float vb[4] = {v4.x, v4.y, v4.z, v4.w};
            #pragma unroll
            for (int i = 0; i < 4; i++) {
                float p = Ss[(r0 + i) * 64 + k];
                #pragma unroll
                for (int j = 0; j < 4; j++)
                    acc[i][j] = fmaf(p, vb[j], acc[i][j]);
            }
        }
        __syncthreads();
    }

    #pragma unroll
    for (int i = 0; i < 4; i++) {
        float inv = 1.0f / l_s[r0 + i];
        float o0 = acc[i][0] * inv, o1 = acc[i][1] * inv;
        float o2 = acc[i][2] * inv, o3 = acc[i][3] * inv;
        uint32_t h01 = bf16x2_of(o0, o1);
        uint32_t h23 = bf16x2_of(o2, o3);
        float e0 = o0 - __uint_as_float(h01 << 16);
        float e1 = o1 - __uint_as_float(h01 & 0xffff0000u);
        float e2 = o2 - __uint_as_float(h23 << 16);
        float e3 = o3 - __uint_as_float(h23 & 0xffff0000u);
        size_t idx = (size_t)(b * TT + t0 + r0 + i) * CC + h * HD + c0;
        *(uint2*)&oh[idx >> 1] = make_uint2(h01, h23);
        *(uint2*)&ol[idx >> 1] = make_uint2(bf16x2_of(e0, e1), bf16x2_of(e2, e3));
    }
}

// ---------------------------------------------------------------------------
// Launch
// ---------------------------------------------------------------------------
extern "C" void kernel_launch(void* const* d_in, const int* in_sizes, int n_in,
                              void* d_out, int out_size)
{
    const float* x      = (const float*)d_in[0];
    const float* qkv_w  = (const float*)d_in[1];
    const float* qkv_b  = (const float*)d_in[2];
    const float* out_w  = (const float*)d_in[3];
    const float* out_b  = (const float*)d_in[4];
    float* out = (float*)d_out;

    float *qkv_buf;
    uint32_t *xh, *xl, *w1h, *w1l, *w2h, *w2l, *ath, *atl;
    cudaGetSymbolAddress((void**)&qkv_buf, g_qkv);
    cudaGetSymbolAddress((void**)&xh, g_xh);   cudaGetSymbolAddress((void**)&xl, g_xl);
    cudaGetSymbolAddress((void**)&w1h, g_w1h); cudaGetSymbolAddress((void**)&w1l, g_w1l);
    cudaGetSymbolAddress((void**)&w2h, g_w2h); cudaGetSymbolAddress((void**)&w2l, g_w2l);
    cudaGetSymbolAddress((void**)&ath, g_ath); cudaGetSymbolAddress((void**)&atl, g_atl);

    const int attn_smem = (4 * 4096 + 3 * 64) * (int)sizeof(float);
    cudaFuncSetAttribute(attn_kernel, cudaFuncAttributeMaxDynamicSharedMemorySize, attn_smem);
    cudaFuncSetAttribute(gemm_mma, cudaFuncAttributeMaxDynamicSharedMemorySize, GEMM_DSM);

    // 0) split inputs/weights to bf16 hi/lo
    {
        int n4 = MTOK * CC / 4;
        split_bf16<<<n4 / 256, 256>>>((const float4*)x, xh, xl, n4);
        n4 = C3 * CC / 4;
        split_bf16<<<n4 / 256, 256>>>((const float4*)qkv_w, w1h, w1l, n4);
        n4 = CC * CC / 4;
        split_bf16<<<n4 / 256, 256>>>((const float4*)out_w, w2h, w2l, n4);
    }
    // 1) QKV projection (tensor cores, split bf16)
    {
        dim3 grid(C3 / 128, MTOK / 128);
        gemm_mma<<<grid, 256, GEMM_DSM>>>(xh, xl, w1h, w1l, qkv_b, qkv_buf, MTOK, C3, CC);
    }
    // 2) Causal flash attention (fp32), writes bf16 hi/lo
    {
        dim3 grid(TT / 64, HH, BB);
        attn_kernel<<<grid, 256, attn_smem>>>(qkv_buf, ath, atl);
    }
    // 3) Output projection (tensor cores, split bf16)
    {
        dim3 grid(CC / 128, MTOK / 128);
        gemm_mma<<<grid, 256, GEMM_DSM>>>(ath, atl, w2h, w2l, out_b, out, MTOK, CC, CC);
    }
}

// round 4
// speedup vs baseline: 2.6860x; 1.9424x over previous
#include <cuda_runtime.h>
#include <cuda_bf16.h>
#include <cstdint>

// Problem constants
#define BB 4
#define TT 2048
#define CC 1024
#define HH 16
#define HD 64
#define MTOK (BB*TT)        // 8192
#define C3  (3*CC)          // 3072

// Scratch (allocation-guard-safe: __device__ globals). bf16 pairs stored as u32.
__device__ uint32_t g_xh[(size_t)MTOK * CC / 2],   g_xl[(size_t)MTOK * CC / 2];
__device__ uint32_t g_w1h[(size_t)C3 * CC / 2],    g_w1l[(size_t)C3 * CC / 2];
__device__ uint32_t g_w2h[(size_t)CC * CC / 2],    g_w2l[(size_t)CC * CC / 2];
__device__ uint32_t g_qkvh[(size_t)MTOK * C3 / 2], g_qkvl[(size_t)MTOK * C3 / 2];
__device__ uint32_t g_ath[(size_t)MTOK * CC / 2],  g_atl[(size_t)MTOK * CC / 2];

// ---------------------------------------------------------------------------
// Helpers (target-portable: mma.sync / ldmatrix / cp.async only)
// ---------------------------------------------------------------------------
__device__ __forceinline__ uint32_t smem_u32(const void* p) {
    uint32_t a;
    asm("{ .reg .u64 t; cvta.to.shared.u64 t, %1; cvt.u32.u64 %0, t; }" : "=r"(a) : "l"(p));
    return a;
}
// pack (lo,hi) -> bf16x2 with 'lo' in LOW half
__device__ __forceinline__ uint32_t bf16x2_of(float lo, float hi) {
    uint32_t r;
    asm("cvt.rn.bf16x2.f32 %0, %1, %2;" : "=r"(r) : "f"(hi), "f"(lo));
    return r;
}
__device__ __forceinline__ void cp16(uint32_t s, const void* g) {
    asm volatile("cp.async.cg.shared.global [%0], [%1], 16;" :: "r"(s), "l"(g) : "memory");
}
__device__ __forceinline__ void cpcommit() {
    asm volatile("cp.async.commit_group;" ::: "memory");
}
__device__ __forceinline__ void cpwait0() { asm volatile("cp.async.wait_group 0;" ::: "memory"); }
__device__ __forceinline__ void cpwait1() { asm volatile("cp.async.wait_group 1;" ::: "memory"); }
__device__ __forceinline__ void ldsm4(uint32_t* r, uint32_t a) {
    asm volatile("ldmatrix.sync.aligned.m8n8.x4.shared.b16 {%0,%1,%2,%3}, [%4];"
        : "=r"(r[0]), "=r"(r[1]), "=r"(r[2]), "=r"(r[3]) : "r"(a));
}
__device__ __forceinline__ void ldsm4t(uint32_t* r, uint32_t a) {
    asm volatile("ldmatrix.sync.aligned.m8n8.x4.trans.shared.b16 {%0,%1,%2,%3}, [%4];"
        : "=r"(r[0]), "=r"(r[1]), "=r"(r[2]), "=r"(r[3]) : "r"(a));
}
__device__ __forceinline__ void mma16816(float* c, const uint32_t* a, const uint32_t* b) {
    asm volatile("mma.sync.aligned.m16n8k16.row.col.f32.bf16.bf16.f32 "
        "{%0,%1,%2,%3}, {%4,%5,%6,%7}, {%8,%9}, {%0,%1,%2,%3};"
        : "+f"(c[0]), "+f"(c[1]), "+f"(c[2]), "+f"(c[3])
        : "r"(a[0]), "r"(a[1]), "r"(a[2]), "r"(a[3]), "r"(b[0]), "r"(b[1]));
}

// ---------------------------------------------------------------------------
// fp32 -> bf16 hi/lo split (elementwise)
// ---------------------------------------------------------------------------
__global__ void split_bf16(const float4* __restrict__ in, uint32_t* __restrict__ hi,
                           uint32_t* __restrict__ lo, int n4)
{
    int i = blockIdx.x * blockDim.x + threadIdx.x;
    if (i >= n4) return;
    float4 f = in[i];
    uint32_t h01 = bf16x2_of(f.x, f.y);
    uint32_t h23 = bf16x2_of(f.z, f.w);
    float r0 = f.x - __uint_as_float(h01 << 16);
    float r1 = f.y - __uint_as_float(h01 & 0xffff0000u);
    float r2 = f.z - __uint_as_float(h23 << 16);
    float r3 = f.w - __uint_as_float(h23 & 0xffff0000u);
    *(uint2*)&hi[2 * i] = make_uint2(h01, h23);
    *(uint2*)&lo[2 * i] = make_uint2(bf16x2_of(r0, r1), bf16x2_of(r2, r3));
}

// ---------------------------------------------------------------------------
// Split-precision bf16 GEMM via mma.sync (pass-reordered for MMA ILP):
//   Out[m][n] = sum_k A[m][k]*W[n][k] + bias[n],  D = Ah*Bh + Ah*Bl + Al*Bh
// 128x128x32 CTA tile, 8 warps (4M x 2N), 3-stage cp.async pipeline.
// SPLIT_OUT=true writes bf16 hi/lo u32 arrays; else fp32.
// ---------------------------------------------------------------------------
#define BK 32
#define STAGES 3
#define SBYTES 32768
#define GEMM_DSM (STAGES * SBYTES + 1024)

template<bool SPLIT_OUT>
__global__ void __launch_bounds__(256, 1)
gemm_mma(const uint32_t* __restrict__ Ah2, const uint32_t* __restrict__ Al2,
         const uint32_t* __restrict__ Bh2, const uint32_t* __restrict__ Bl2,
         const float* __restrict__ bias, float* __restrict__ OutF,
         uint32_t* __restrict__ OutH, uint32_t* __restrict__ OutL,
         int M, int N, int K)
{
    extern __shared__ char dsm[];
    const uint32_t sbase = (smem_u32(dsm) + 1023u) & ~1023u;

    const int tid  = threadIdx.x;
    const int lane = tid & 31;
    const int warp = tid >> 5;
    const int wm = warp & 3;
    const int wn = warp >> 2;
    const int m0 = blockIdx.y * 128;
    const int n0 = blockIdx.x * 128;

    const int lr  = tid >> 1;
    const int lkc = (tid & 1) * 2;

    const char* pAh = (const char*)Ah2 + ((size_t)(m0 + lr) * K) * 2;
    const char* pAl = (const char*)Al2 + ((size_t)(m0 + lr) * K) * 2;
    const char* pBh = (const char*)Bh2 + ((size_t)(n0 + lr) * K) * 2;
    const char* pBl = (const char*)Bl2 + ((size_t)(n0 + lr) * K) * 2;
    const int rsw = (lr >> 1) & 3;

    float acc[2][8][4] = {};
    const int NKI = K / BK;

    auto load_stage = [&](int s, int it) {
        const uint32_t ss = sbase + s * SBYTES;
        const int gko = it * BK * 2;
        #pragma unroll
        for (int i = 0; i < 2; i++) {
            const int kc = lkc + i;
            const uint32_t so = (uint32_t)(lr * 64 + ((kc ^ rsw) << 4));
            const int go = gko + kc * 16;
            cp16(ss + so,          pAh + go);
            cp16(ss + 8192 + so,   pAl + go);
            cp16(ss + 16384 + so,  pBh + go);
            cp16(ss + 24576 + so,  pBl + go);
        }
    };

    auto compute_stage = [&](int s) {
        const uint32_t ss = sbase + s * SBYTES;
        #pragma unroll
        for (int ks = 0; ks < 2; ks++) {
            uint32_t ah[2][4], al[2][4];
            #pragma unroll
            for (int mt = 0; mt < 2; mt++) {
                int row = wm * 32 + mt * 16 + (lane & 15);
                int kc  = ks * 2 + (lane >> 4);
                uint32_t so = (uint32_t)(row * 64 + ((kc ^ ((row >> 1) & 3)) << 4));
                ldsm4(ah[mt], ss + so);
                ldsm4(al[mt], ss + 8192 + so);
            }
            uint32_t bh[4][4], bl[4][4];
            #pragma unroll
            for (int jj = 0; jj < 4; jj++) {
                int row = wn * 64 + jj * 16 + (lane & 7) + ((lane >> 4) << 3);
                int kc  = ks * 2 + ((lane >> 3) & 1);
                uint32_t so = (uint32_t)(row * 64 + ((kc ^ ((row >> 1) & 3)) << 4));
                ldsm4(bh[jj], ss + 16384 + so);
                ldsm4(bl[jj], ss + 24576 + so);
            }
            // pass-reordered: consecutive MMAs hit different accumulators
            #pragma unroll
            for (int mt = 0; mt < 2; mt++)
                #pragma unroll
                for (int nt = 0; nt < 8; nt++)
                    mma16816(acc[mt][nt], ah[mt], &bh[nt >> 1][(nt & 1) * 2]);
            #pragma unroll
            for (int mt = 0; mt < 2; mt++)
                #pragma unroll
                for (int nt = 0; nt < 8; nt++)
                    mma16816(acc[mt][nt], ah[mt], &bl[nt >> 1][(nt & 1) * 2]);
            #pragma unroll
            for (int mt = 0; mt < 2; mt++)
                #pragma unroll
                for (int nt = 0; nt < 8; nt++)
                    mma16816(acc[mt][nt], al[mt], &bh[nt >> 1][(nt & 1) * 2]);
        }
    };

    #pragma unroll
    for (int s = 0; s < STAGES - 1; s++) { load_stage(s, s); cpcommit(); }

    for (int it = 0; it < NKI; it++) {
        asm volatile("cp.async.wait_group %0;" :: "n"(STAGES - 2) : "memory");
        __syncthreads();
        const int nit = it + STAGES - 1;
        if (nit < NKI) load_stage(nit % STAGES, nit);
        cpcommit();
        compute_stage(it % STAGES);
    }

    const int rr = lane >> 2;
    const int cc = (lane & 3) * 2;
    #pragma unroll
    for (int mt = 0; mt < 2; mt++)
        #pragma unroll
        for (int nt = 0; nt < 8; nt++) {
            const int col = n0 + wn * 64 + nt * 8 + cc;
            const float b0 = bias[col], b1 = bias[col + 1];
            #pragma unroll
            for (int hf = 0; hf < 2; hf++) {
                const int row = m0 + wm * 32 + mt * 16 + rr + hf * 8;
                float v0 = acc[mt][nt][hf * 2 + 0] + b0;
                float v1 = acc[mt][nt][hf * 2 + 1] + b1;
                if (SPLIT_OUT) {
                    uint32_t h01 = bf16x2_of(v0, v1);
                    float e0 = v0 - __uint_as_float(h01 << 16);
                    float e1 = v1 - __uint_as_float(h01 & 0xffff0000u);
                    size_t idx = ((size_t)row * N + col) >> 1;
                    OutH[idx] = h01;
                    OutL[idx] = bf16x2_of(e0, e1);
                } else {
                    *(float2*)&OutF[(size_t)row * N + col] = make_float2(v0, v1);
                }
            }
        }
}

// ---------------------------------------------------------------------------
// Flash attention (causal) on mma.sync with split-bf16 inputs/outputs.
// Grid (T/128, H, B), 256 threads (8 warps; warp w owns q-rows w*16..+15).
// S = Qh*Kh + Qh*Kl + Ql*Kh ; P split ; O += Ph*Vh + Ph*Vl + Pl*Vh.
// smem: Qh|Ql (32KB) + 2 stages x (Kh|Kl|Vh|Vl = 32KB). Row-chunk XOR swizzle.
// ---------------------------------------------------------------------------
#define QTILE 128
#define KTILE 64
#define ASTAGE 32768
#define ATTN_DSM (32768 + 2 * ASTAGE + 1024)

__device__ __forceinline__ uint32_t swz(uint32_t base, int row, int chunk) {
    return base + (uint32_t)(row * 128) + (uint32_t)((chunk ^ (row & 7)) << 4);
}

__global__ void __launch_bounds__(256, 1)
attn_mma(const uint32_t* __restrict__ qkvh, const uint32_t* __restrict__ qkvl,
         uint32_t* __restrict__ oh, uint32_t* __restrict__ ol)
{
    extern __shared__ char dsm[];
    const uint32_t sb = (smem_u32(dsm) + 1023u) & ~1023u;
    const uint32_t sQh = sb, sQl = sb + 16384, sStage = sb + 32768;

    const int tid = threadIdx.x;
    const int lane = tid & 31;
    const int wm = tid >> 5;                  // warp 0..7 -> q rows wm*16..+15
    const int qt = blockIdx.x;
    const int h  = blockIdx.y;
    const int b  = blockIdx.z;
    const int t0 = qt * QTILE;
    const int bT = b * TT;

    const char* ph = (const char*)qkvh;
    const char* pl = (const char*)qkvl;

    const int nkt = 2 * (qt + 1);

    // ---- loaders ----
    auto load_q = [&]() {
        #pragma unroll
        for (int i = 0; i < 4; i++) {
            int idx = i * 256 + tid;
            int r = idx >> 3, c = idx & 7;
            size_t gb = ((size_t)(bT + t0 + r) * C3 + h * HD) * 2 + c * 16;
            cp16(swz(sQh, r, c), ph + gb);
            cp16(swz(sQl, r, c), pl + gb);
        }
    };
    auto load_kv = [&](int kt, int buf) {
        const uint32_t ss = sStage + buf * ASTAGE;
        int r = tid >> 2;
        int cbase = (tid & 3) * 2;
        size_t rowg = (size_t)(bT + kt * KTILE + r) * C3;
        size_t kb = (rowg + CC + h * HD) * 2;
        size_t vb = (rowg + 2 * CC + h * HD) * 2;
        #pragma unroll
        for (int j = 0; j < 2; j++) {
            int c = cbase + j;
            cp16(swz(ss,          r, c), ph + kb + c * 16);
            cp16(swz(ss + 8192,   r, c), pl + kb + c * 16);
            cp16(swz(ss + 16384,  r, c), ph + vb + c * 16);
            cp16(swz(ss + 24576,  r, c), pl + vb + c * 16);
        }
    };

    // ---- prologue ----
    load_q();
    load_kv(0, 0);
    cpcommit();

    uint32_t qh[4][4], ql[4][4];
    float oacc[8][4] = {};
    float m_prev[2] = {-1e30f, -1e30f};
    float l_run[2] = {0.0f, 0.0f};
    const float scale = 0.125f;
    bool qload = false;

    for (int kt = 0; kt < nkt; kt++) {
        if (kt + 1 < nkt) { load_kv(kt + 1, (kt + 1) & 1); cpcommit(); cpwait1(); }
        else cpwait0();
        __syncthreads();

        if (!qload) {   // Q frags (A layout), once
            qload = true;
            #pragma unroll
            for (int ks = 0; ks < 4; ks++) {
                int row = wm * 16 + (lane & 15);
                int c = ks * 2 + (lane >> 4);
                ldsm4(qh[ks], swz(sQh, row, c));
                ldsm4(ql[ks], swz(sQl, row, c));
            }
        }

        const uint32_t ss = sStage + (kt & 1) * ASTAGE;
        const bool doCompute = (kt * KTILE) <= (t0 + wm * 16 + 15);
        if (doCompute) {
            // ---- S = Q K^T (split, 3 passes) ----
            float sacc[8][4] = {};
            #pragma unroll
            for (int ks = 0; ks < 4; ks++) {
                uint32_t bh[4][4], bl[4][4];
                #pragma unroll
                for (int jj = 0; jj < 4; jj++) {
                    int row = jj * 16 + (lane & 7) + ((lane >> 4) << 3);
                    int c = ks * 2 + ((lane >> 3) & 1);
                    ldsm4(bh[jj], swz(ss, row, c));
                    ldsm4(bl[jj], swz(ss + 8192, row, c));
                }
                #pragma unroll
                for (int nt = 0; nt < 8; nt++)
                    mma16816(sacc[nt], qh[ks], &bh[nt >> 1][(nt & 1) * 2]);
                #pragma unroll
                for (int nt = 0; nt < 8; nt++)
                    mma16816(sacc[nt], qh[ks], &bl[nt >> 1][(nt & 1) * 2]);
                #pragma unroll
                for (int nt = 0; nt < 8; nt++)
                    mma16816(sacc[nt], ql[ks], &bh[nt >> 1][(nt & 1) * 2]);
            }

            // ---- scale + causal mask ----
            const bool anyMask = (kt * KTILE + KTILE - 1) > (t0 + wm * 16);
            #pragma unroll
            for (int nt = 0; nt < 8; nt++)
                #pragma unroll
                for (int e = 0; e < 4; e++) {
                    float v = sacc[nt][e] * scale;
                    if (anyMask) {
                        int rg = t0 + wm * 16 + (lane >> 2) + (e >> 1) * 8;
                        int cg = kt * KTILE + nt * 8 + (lane & 3) * 2 + (e & 1);
                        if (cg > rg) v = -1e30f;
                    }
                    sacc[nt][e] = v;
                }

            // ---- online softmax (rows split across quad lanes) ----
            #pragma unroll
            for (int rh = 0; rh < 2; rh++) {
                float mloc = -1e30f;
                #pragma unroll
                for (int nt = 0; nt < 8; nt++)
                    mloc = fmaxf(mloc, fmaxf(sacc[nt][rh * 2], sacc[nt][rh * 2 + 1]));
                mloc = fmaxf(mloc, __shfl_xor_sync(0xffffffffu, mloc, 1));
                mloc = fmaxf(mloc, __shfl_xor_sync(0xffffffffu, mloc, 2));
                float mnew = fmaxf(m_prev[rh], mloc);
                float corr = __expf(m_prev[rh] - mnew);
                m_prev[rh] = mnew;
                float ls = 0.0f;
                #pragma unroll
                for (int nt = 0; nt < 8; nt++) {
                    float p0 = __expf(sacc[nt][rh * 2]     - mnew);
                    float p1 = __expf(sacc[nt][rh * 2 + 1] - mnew);
                    sacc[nt][rh * 2] = p0; sacc[nt][rh * 2 + 1] = p1;
                    ls += p0 + p1;
                }
                ls += __shfl_xor_sync(0xffffffffu, ls, 1);
                ls += __shfl_xor_sync(0xffffffffu, ls, 2);
                l_run[rh] = l_run[rh] * corr + ls;
                #pragma unroll
                for (int nt = 0; nt < 8; nt++) {
                    oacc[nt][rh * 2]     *= corr;
                    oacc[nt][rh * 2 + 1] *= corr;
                }
            }

            // ---- O += P V (split, 3 passes); P frags from S accs ----
            #pragma unroll
            for (int jp = 0; jp < 4; jp++) {
                uint32_t pa[4], pal[4];
                {
                    const float* f0 = sacc[2 * jp];
                    const float* f1 = sacc[2 * jp + 1];
                    pa[0] = bf16x2_of(f0[0], f0[1]);
                    pa[1] = bf16x2_of(f0[2], f0[3]);
                    pa[2] = bf16x2_of(f1[0], f1[1]);
                    pa[3] = bf16x2_of(f1[2], f1[3]);
                    pal[0] = bf16x2_of(f0[0] - __uint_as_float(pa[0] << 16),
                                       f0[1] - __uint_as_float(pa[0] & 0xffff0000u));
                    pal[1] = bf16x2_of(f0[2] - __uint_as_float(pa[1] << 16),
                                       f0[3] - __uint_as_float(pa[1] & 0xffff0000u));
                    pal[2] = bf16x2_of(f1[0] - __uint_as_float(pa[2] << 16),
                                       f1[1] - __uint_as_float(pa[2] & 0xffff0000u));
                    pal[3] = bf16x2_of(f1[2] - __uint_as_float(pa[3] << 16),
                                       f1[3] - __uint_as_float(pa[3] & 0xffff0000u));
                }
                uint32_t vh[4][4], vl[4][4];
                #pragma unroll
                for (int jd = 0; jd < 4; jd++) {
                    int row = jp * 16 + (lane & 7) + (((lane >> 3) & 1) << 3);
                    int c = 2 * jd + (lane >> 4);
                    ldsm4t(vh[jd], swz(ss + 16384, row, c));
                    ldsm4t(vl[jd], swz(ss + 24576, row, c));
                }
                #pragma unroll
                for (int nt = 0; nt < 8; nt++)
                    mma16816(oacc[nt], pa, &vh[nt >> 1][(nt & 1) * 2]);
                #pragma unroll
                for (int nt = 0; nt < 8; nt++)
                    mma16816(oacc[nt], pa, &vl[nt >> 1][(nt & 1) * 2]);
                #pragma unroll
                for (int nt = 0; nt < 8; nt++)
                    mma16816(oacc[nt], pal, &vh[nt >> 1][(nt & 1) * 2]);
            }
        }
        __syncthreads();
    }

    // ---- epilogue: normalize, split to bf16 hi/lo, store ----
    float inv0 = 1.0f / l_run[0];
    float inv1 = 1.0f / l_run[1];
    #pragma unroll
    for (int nt = 0; nt < 8; nt++)
        #pragma unroll
        for (int rh = 0; rh < 2; rh++) {
            float iv = rh ? inv1 : inv0;
            float o0 = oacc[nt][rh * 2] * iv;
            float o1 = oacc[nt][rh * 2 + 1] * iv;
            uint32_t h01 = bf16x2_of(o0, o1);
            float e0 = o0 - __uint_as_float(h01 << 16);
            float e1 = o1 - __uint_as_float(h01 & 0xffff0000u);
            size_t token = (size_t)(bT + t0 + wm * 16 + (lane >> 2) + rh * 8);
            size_t idx = (token * CC + h * HD + nt * 8 + (lane & 3) * 2) >> 1;
            oh[idx] = h01;
            ol[idx] = bf16x2_of(e0, e1);
        }
}

// ---------------------------------------------------------------------------
// Launch
// ---------------------------------------------------------------------------
extern "C" void kernel_launch(void* const* d_in, const int* in_sizes, int n_in,
                              void* d_out, int out_size)
{
    const float* x      = (const float*)d_in[0];
    const float* qkv_w  = (const float*)d_in[1];
    const float* qkv_b  = (const float*)d_in[2];
    const float* out_w  = (const float*)d_in[3];
    const float* out_b  = (const float*)d_in[4];
    float* out = (float*)d_out;

    uint32_t *xh, *xl, *w1h, *w1l, *w2h, *w2l, *qh, *ql, *ath, *atl;
    cudaGetSymbolAddress((void**)&xh, g_xh);     cudaGetSymbolAddress((void**)&xl, g_xl);
    cudaGetSymbolAddress((void**)&w1h, g_w1h);   cudaGetSymbolAddress((void**)&w1l, g_w1l);
    cudaGetSymbolAddress((void**)&w2h, g_w2h);   cudaGetSymbolAddress((void**)&w2l, g_w2l);
    cudaGetSymbolAddress((void**)&qh, g_qkvh);   cudaGetSymbolAddress((void**)&ql, g_qkvl);
    cudaGetSymbolAddress((void**)&ath, g_ath);   cudaGetSymbolAddress((void**)&atl, g_atl);

    cudaFuncSetAttribute(gemm_mma<true>,  cudaFuncAttributeMaxDynamicSharedMemorySize, GEMM_DSM);
    cudaFuncSetAttribute(gemm_mma<false>, cudaFuncAttributeMaxDynamicSharedMemorySize, GEMM_DSM);
    cudaFuncSetAttribute(attn_mma, cudaFuncAttributeMaxDynamicSharedMemorySize, ATTN_DSM);

    // 0) split inputs/weights to bf16 hi/lo
    {
        int n4 = MTOK * CC / 4;
        split_bf16<<<n4 / 256, 256>>>((const float4*)x, xh, xl, n4);
        n4 = C3 * CC / 4;
        split_bf16<<<n4 / 256, 256>>>((const float4*)qkv_w, w1h, w1l, n4);
        n4 = CC * CC / 4;
        split_bf16<<<n4 / 256, 256>>>((const float4*)out_w, w2h, w2l, n4);
    }
    // 1) QKV projection -> split bf16 qkv
    {
        dim3 grid(C3 / 128, MTOK / 128);
        gemm_mma<true><<<grid, 256, GEMM_DSM>>>(xh, xl, w1h, w1l, qkv_b,
                                                nullptr, qh, ql, MTOK, C3, CC);
    }
    // 2) Causal flash attention (tensor cores) -> split bf16
    {
        dim3 grid(TT / QTILE, HH, BB);
        attn_mma<<<grid, 256, ATTN_DSM>>>(qh, ql, ath, atl);
    }
    // 3) Output projection -> fp32
    {
        dim3 grid(CC / 128, MTOK / 128);
        gemm_mma<false><<<grid, 256, GEMM_DSM>>>(ath, atl, w2h, w2l, out_b,
                                                 out, nullptr, nullptr, MTOK, CC, CC);
    }
}

// round 5
// speedup vs baseline: 2.9478x; 1.0974x over previous
#include <cuda_runtime.h>
#include <cuda_bf16.h>
#include <cstdint>

// Problem constants
#define BB 4
#define TT 2048
#define CC 1024
#define HH 16
#define HD 64
#define MTOK (BB*TT)        // 8192
#define C3  (3*CC)          // 3072

// Scratch (allocation-guard-safe: __device__ globals). bf16 pairs stored as u32.
__device__ uint32_t g_xh[(size_t)MTOK * CC / 2],   g_xl[(size_t)MTOK * CC / 2];
__device__ uint32_t g_w1h[(size_t)C3 * CC / 2],    g_w1l[(size_t)C3 * CC / 2];
__device__ uint32_t g_w2h[(size_t)CC * CC / 2],    g_w2l[(size_t)CC * CC / 2];
__device__ uint32_t g_qkvh[(size_t)MTOK * C3 / 2], g_qkvl[(size_t)MTOK * C3 / 2];
__device__ uint32_t g_ath[(size_t)MTOK * CC / 2],  g_atl[(size_t)MTOK * CC / 2];

// ---------------------------------------------------------------------------
// Helpers (target-portable: mma.sync / ldmatrix / cp.async only)
// ---------------------------------------------------------------------------
__device__ __forceinline__ uint32_t smem_u32(const void* p) {
    uint32_t a;
    asm("{ .reg .u64 t; cvta.to.shared.u64 t, %1; cvt.u32.u64 %0, t; }" : "=r"(a) : "l"(p));
    return a;
}
// pack (lo,hi) -> bf16x2 with 'lo' in LOW half
__device__ __forceinline__ uint32_t bf16x2_of(float lo, float hi) {
    uint32_t r;
    asm("cvt.rn.bf16x2.f32 %0, %1, %2;" : "=r"(r) : "f"(hi), "f"(lo));
    return r;
}
__device__ __forceinline__ void cp16(uint32_t s, const void* g) {
    asm volatile("cp.async.cg.shared.global [%0], [%1], 16;" :: "r"(s), "l"(g) : "memory");
}
__device__ __forceinline__ void cpcommit() {
    asm volatile("cp.async.commit_group;" ::: "memory");
}
__device__ __forceinline__ void cpwait0() { asm volatile("cp.async.wait_group 0;" ::: "memory"); }
__device__ __forceinline__ void cpwait1() { asm volatile("cp.async.wait_group 1;" ::: "memory"); }
__device__ __forceinline__ void ldsm4(uint32_t* r, uint32_t a) {
    asm volatile("ldmatrix.sync.aligned.m8n8.x4.shared.b16 {%0,%1,%2,%3}, [%4];"
        : "=r"(r[0]), "=r"(r[1]), "=r"(r[2]), "=r"(r[3]) : "r"(a));
}
__device__ __forceinline__ void ldsm4t(uint32_t* r, uint32_t a) {
    asm volatile("ldmatrix.sync.aligned.m8n8.x4.trans.shared.b16 {%0,%1,%2,%3}, [%4];"
        : "=r"(r[0]), "=r"(r[1]), "=r"(r[2]), "=r"(r[3]) : "r"(a));
}
__device__ __forceinline__ void mma16816(float* c, const uint32_t* a, const uint32_t* b) {
    asm volatile("mma.sync.aligned.m16n8k16.row.col.f32.bf16.bf16.f32 "
        "{%0,%1,%2,%3}, {%4,%5,%6,%7}, {%8,%9}, {%0,%1,%2,%3};"
        : "+f"(c[0]), "+f"(c[1]), "+f"(c[2]), "+f"(c[3])
        : "r"(a[0]), "r"(a[1]), "r"(a[2]), "r"(a[3]), "r"(b[0]), "r"(b[1]));
}

// ---------------------------------------------------------------------------
// fp32 -> bf16 hi/lo split (elementwise)
// ---------------------------------------------------------------------------
__global__ void split_bf16(const float4* __restrict__ in, uint32_t* __restrict__ hi,
                           uint32_t* __restrict__ lo, int n4)
{
    int i = blockIdx.x * blockDim.x + threadIdx.x;
    if (i >= n4) return;
    float4 f = in[i];
    uint32_t h01 = bf16x2_of(f.x, f.y);
    uint32_t h23 = bf16x2_of(f.z, f.w);
    float r0 = f.x - __uint_as_float(h01 << 16);
    float r1 = f.y - __uint_as_float(h01 & 0xffff0000u);
    float r2 = f.z - __uint_as_float(h23 << 16);
    float r3 = f.w - __uint_as_float(h23 & 0xffff0000u);
    *(uint2*)&hi[2 * i] = make_uint2(h01, h23);
    *(uint2*)&lo[2 * i] = make_uint2(bf16x2_of(r0, r1), bf16x2_of(r2, r3));
}

// ---------------------------------------------------------------------------
// Split-precision bf16 GEMM via mma.sync, occupancy-optimized:
//   Out[m][n] = sum_k A[m][k]*W[n][k] + bias[n],  D = Ah*Bh + Ah*Bl + Al*Bh
// CTA tile 128x64x32, warp tile 32x32, 8 warps (4M x 2N), regs<=128 ->
// 2 CTAs/SM (4 warps/SMSP). 4-stage cp.async pipeline (24 KB/stage).
// SPLIT_OUT=true writes bf16 hi/lo u32 arrays; else fp32.
// ---------------------------------------------------------------------------
#define BK 32
#define STAGES 4
#define SBYTES 24576     // Ah 8K | Al 8K | Bh 4K | Bl 4K
#define GEMM_DSM (STAGES * SBYTES + 1024)

template<bool SPLIT_OUT>
__global__ void __launch_bounds__(256, 2)
gemm_mma(const uint32_t* __restrict__ Ah2, const uint32_t* __restrict__ Al2,
         const uint32_t* __restrict__ Bh2, const uint32_t* __restrict__ Bl2,
         const float* __restrict__ bias, float* __restrict__ OutF,
         uint32_t* __restrict__ OutH, uint32_t* __restrict__ OutL,
         int M, int N, int K)
{
    extern __shared__ char dsm[];
    const uint32_t sbase = (smem_u32(dsm) + 1023u) & ~1023u;

    const int tid  = threadIdx.x;
    const int lane = tid & 31;
    const int warp = tid >> 5;
    const int wm = warp & 3;        // 4 warps along M (32 rows each)
    const int wn = warp >> 2;       // 2 warps along N (32 cols each)
    const int m0 = blockIdx.y * 128;
    const int n0 = blockIdx.x * 64;

    // A loader: r = tid>>1 (0..127), chunks (tid&1)*2 .. +1
    const int alr  = tid >> 1;
    const int alkc = (tid & 1) * 2;
    // B loader: r = tid>>2 (0..63), chunk tid&3
    const int blr  = tid >> 2;
    const int blkc = tid & 3;

    const char* pAh = (const char*)Ah2 + ((size_t)(m0 + alr) * K) * 2;
    const char* pAl = (const char*)Al2 + ((size_t)(m0 + alr) * K) * 2;
    const char* pBh = (const char*)Bh2 + ((size_t)(n0 + blr) * K) * 2;
    const char* pBl = (const char*)Bl2 + ((size_t)(n0 + blr) * K) * 2;
    const int arsw = (alr >> 1) & 3;
    const int brsw = (blr >> 1) & 3;

    float acc[2][4][4] = {};
    const int NKI = K / BK;

    auto load_stage = [&](int s, int it) {
        const uint32_t ss = sbase + s * SBYTES;
        const int gko = it * BK * 2;
        #pragma unroll
        for (int i = 0; i < 2; i++) {
            const int kc = alkc + i;
            const uint32_t so = (uint32_t)(alr * 64 + ((kc ^ arsw) << 4));
            const int go = gko + kc * 16;
            cp16(ss + so,        pAh + go);
            cp16(ss + 8192 + so, pAl + go);
        }
        {
            const uint32_t so = (uint32_t)(blr * 64 + ((blkc ^ brsw) << 4));
            const int go = gko + blkc * 16;
            cp16(ss + 16384 + so, pBh + go);
            cp16(ss + 20480 + so, pBl + go);
        }
    };

    auto compute_stage = [&](int s) {
        const uint32_t ss = sbase + s * SBYTES;
        #pragma unroll
        for (int ks = 0; ks < 2; ks++) {
            uint32_t ah[2][4], al[2][4];
            #pragma unroll
            for (int mt = 0; mt < 2; mt++) {
                int row = wm * 32 + mt * 16 + (lane & 15);
                int kc  = ks * 2 + (lane >> 4);
                uint32_t so = (uint32_t)(row * 64 + ((kc ^ ((row >> 1) & 3)) << 4));
                ldsm4(ah[mt], ss + so);
                ldsm4(al[mt], ss + 8192 + so);
            }
            uint32_t bh[2][4], bl[2][4];
            #pragma unroll
            for (int jj = 0; jj < 2; jj++) {
                int row = wn * 32 + jj * 16 + (lane & 7) + ((lane >> 4) << 3);
                int kc  = ks * 2 + ((lane >> 3) & 1);
                uint32_t so = (uint32_t)(row * 64 + ((kc ^ ((row >> 1) & 3)) << 4));
                ldsm4(bh[jj], ss + 16384 + so);
                ldsm4(bl[jj], ss + 20480 + so);
            }
            // pass-reordered: consecutive MMAs hit different accumulators
            #pragma unroll
            for (int mt = 0; mt < 2; mt++)
                #pragma unroll
                for (int nt = 0; nt < 4; nt++)
                    mma16816(acc[mt][nt], ah[mt], &bh[nt >> 1][(nt & 1) * 2]);
            #pragma unroll
            for (int mt = 0; mt < 2; mt++)
                #pragma unroll
                for (int nt = 0; nt < 4; nt++)
                    mma16816(acc[mt][nt], ah[mt], &bl[nt >> 1][(nt & 1) * 2]);
            #pragma unroll
            for (int mt = 0; mt < 2; mt++)
                #pragma unroll
                for (int nt = 0; nt < 4; nt++)
                    mma16816(acc[mt][nt], al[mt], &bh[nt >> 1][(nt & 1) * 2]);
        }
    };

    #pragma unroll
    for (int s = 0; s < STAGES - 1; s++) { load_stage(s, s); cpcommit(); }

    for (int it = 0; it < NKI; it++) {
        asm volatile("cp.async.wait_group %0;" :: "n"(STAGES - 2) : "memory");
        __syncthreads();
        const int nit = it + STAGES - 1;
        if (nit < NKI) load_stage(nit % STAGES, nit);
        cpcommit();
        compute_stage(it % STAGES);
    }

    const int rr = lane >> 2;
    const int cc = (lane & 3) * 2;
    #pragma unroll
    for (int mt = 0; mt < 2; mt++)
        #pragma unroll
        for (int nt = 0; nt < 4; nt++) {
            const int col = n0 + wn * 32 + nt * 8 + cc;
            const float b0 = bias[col], b1 = bias[col + 1];
            #pragma unroll
            for (int hf = 0; hf < 2; hf++) {
                const int row = m0 + wm * 32 + mt * 16 + rr + hf * 8;
                float v0 = acc[mt][nt][hf * 2 + 0] + b0;
                float v1 = acc[mt][nt][hf * 2 + 1] + b1;
                if (SPLIT_OUT) {
                    uint32_t h01 = bf16x2_of(v0, v1);
                    float e0 = v0 - __uint_as_float(h01 << 16);
                    float e1 = v1 - __uint_as_float(h01 & 0xffff0000u);
                    size_t idx = ((size_t)row * N + col) >> 1;
                    OutH[idx] = h01;
                    OutL[idx] = bf16x2_of(e0, e1);
                } else {
                    *(float2*)&OutF[(size_t)row * N + col] = make_float2(v0, v1);
                }
            }
        }
}

// ---------------------------------------------------------------------------
// Flash attention (causal) on mma.sync with split-bf16 inputs/outputs.
// (unchanged from R4)
// ---------------------------------------------------------------------------
#define QTILE 128
#define KTILE 64
#define ASTAGE 32768
#define ATTN_DSM (32768 + 2 * ASTAGE + 1024)

__device__ __forceinline__ uint32_t swz(uint32_t base, int row, int chunk) {
    return base + (uint32_t)(row * 128) + (uint32_t)((chunk ^ (row & 7)) << 4);
}

__global__ void __launch_bounds__(256, 1)
attn_mma(const uint32_t* __restrict__ qkvh, const uint32_t* __restrict__ qkvl,
         uint32_t* __restrict__ oh, uint32_t* __restrict__ ol)
{
    extern __shared__ char dsm[];
    const uint32_t sb = (smem_u32(dsm) + 1023u) & ~1023u;
    const uint32_t sQh = sb, sQl = sb + 16384, sStage = sb + 32768;

    const int tid = threadIdx.x;
    const int lane = tid & 31;
    const int wm = tid >> 5;
    const int qt = blockIdx.x;
    const int h  = blockIdx.y;
    const int b  = blockIdx.z;
    const int t0 = qt * QTILE;
    const int bT = b * TT;

    const char* ph = (const char*)qkvh;
    const char* pl = (const char*)qkvl;

    const int nkt = 2 * (qt + 1);

    auto load_q = [&]() {
        #pragma unroll
        for (int i = 0; i < 4; i++) {
            int idx = i * 256 + tid;
            int r = idx >> 3, c = idx & 7;
            size_t gb = ((size_t)(bT + t0 + r) * C3 + h * HD) * 2 + c * 16;
            cp16(swz(sQh, r, c), ph + gb);
            cp16(swz(sQl, r, c), pl + gb);
        }
    };
    auto load_kv = [&](int kt, int buf) {
        const uint32_t ss = sStage + buf * ASTAGE;
        int r = tid >> 2;
        int cbase = (tid & 3) * 2;
        size_t rowg = (size_t)(bT + kt * KTILE + r) * C3;
        size_t kb = (rowg + CC + h * HD) * 2;
        size_t vb = (rowg + 2 * CC + h * HD) * 2;
        #pragma unroll
        for (int j = 0; j < 2; j++) {
            int c = cbase + j;
            cp16(swz(ss,          r, c), ph + kb + c * 16);
            cp16(swz(ss + 8192,   r, c), pl + kb + c * 16);
            cp16(swz(ss + 16384,  r, c), ph + vb + c * 16);
            cp16(swz(ss + 24576,  r, c), pl + vb + c * 16);
        }
    };

    load_q();
    load_kv(0, 0);
    cpcommit();

    uint32_t qh[4][4], ql[4][4];
    float oacc[8][4] = {};
    float m_prev[2] = {-1e30f, -1e30f};
    float l_run[2] = {0.0f, 0.0f};
    const float scale = 0.125f;
    bool qload = false;

    for (int kt = 0; kt < nkt; kt++) {
        if (kt + 1 < nkt) { load_kv(kt + 1, (kt + 1) & 1); cpcommit(); cpwait1(); }
        else cpwait0();
        __syncthreads();

        if (!qload) {
            qload = true;
            #pragma unroll
            for (int ks = 0; ks < 4; ks++) {
                int row = wm * 16 + (lane & 15);
                int c = ks * 2 + (lane >> 4);
                ldsm4(qh[ks], swz(sQh, row, c));
                ldsm4(ql[ks], swz(sQl, row, c));
            }
        }

        const uint32_t ss = sStage + (kt & 1) * ASTAGE;
        const bool doCompute = (kt * KTILE) <= (t0 + wm * 16 + 15);
        if (doCompute) {
            float sacc[8][4] = {};
            #pragma unroll
            for (int ks = 0; ks < 4; ks++) {
                uint32_t bh[4][4], bl[4][4];
                #pragma unroll
                for (int jj = 0; jj < 4; jj++) {
                    int row = jj * 16 + (lane & 7) + ((lane >> 4) << 3);
                    int c = ks * 2 + ((lane >> 3) & 1);
                    ldsm4(bh[jj], swz(ss, row, c));
                    ldsm4(bl[jj], swz(ss + 8192, row, c));
                }
                #pragma unroll
                for (int nt = 0; nt < 8; nt++)
                    mma16816(sacc[nt], qh[ks], &bh[nt >> 1][(nt & 1) * 2]);
                #pragma unroll
                for (int nt = 0; nt < 8; nt++)
                    mma16816(sacc[nt], qh[ks], &bl[nt >> 1][(nt & 1) * 2]);
                #pragma unroll
                for (int nt = 0; nt < 8; nt++)
                    mma16816(sacc[nt], ql[ks], &bh[nt >> 1][(nt & 1) * 2]);
            }

            const bool anyMask = (kt * KTILE + KTILE - 1) > (t0 + wm * 16);
            #pragma unroll
            for (int nt = 0; nt < 8; nt++)
                #pragma unroll
                for (int e = 0; e < 4; e++) {
                    float v = sacc[nt][e] * scale;
                    if (anyMask) {
                        int rg = t0 + wm * 16 + (lane >> 2) + (e >> 1) * 8;
                        int cg = kt * KTILE + nt * 8 + (lane & 3) * 2 + (e & 1);
                        if (cg > rg) v = -1e30f;
                    }
                    sacc[nt][e] = v;
                }

            #pragma unroll
            for (int rh = 0; rh < 2; rh++) {
                float mloc = -1e30f;
                #pragma unroll
                for (int nt = 0; nt < 8; nt++)
                    mloc = fmaxf(mloc, fmaxf(sacc[nt][rh * 2], sacc[nt][rh * 2 + 1]));
                mloc = fmaxf(mloc, __shfl_xor_sync(0xffffffffu, mloc, 1));
                mloc = fmaxf(mloc, __shfl_xor_sync(0xffffffffu, mloc, 2));
                float mnew = fmaxf(m_prev[rh], mloc);
                float corr = __expf(m_prev[rh] - mnew);
                m_prev[rh] = mnew;
                float ls = 0.0f;
                #pragma unroll
                for (int nt = 0; nt < 8; nt++) {
                    float p0 = __expf(sacc[nt][rh * 2]     - mnew);
                    float p1 = __expf(sacc[nt][rh * 2 + 1] - mnew);
                    sacc[nt][rh * 2] = p0; sacc[nt][rh * 2 + 1] = p1;
                    ls += p0 + p1;
                }
                ls += __shfl_xor_sync(0xffffffffu, ls, 1);
                ls += __shfl_xor_sync(0xffffffffu, ls, 2);
                l_run[rh] = l_run[rh] * corr + ls;
                #pragma unroll
                for (int nt = 0; nt < 8; nt++) {
                    oacc[nt][rh * 2]     *= corr;
                    oacc[nt][rh * 2 + 1] *= corr;
                }
            }

            #pragma unroll
            for (int jp = 0; jp < 4; jp++) {
                uint32_t pa[4], pal[4];
                {
                    const float* f0 = sacc[2 * jp];
                    const float* f1 = sacc[2 * jp + 1];
                    pa[0] = bf16x2_of(f0[0], f0[1]);
                    pa[1] = bf16x2_of(f0[2], f0[3]);
                    pa[2] = bf16x2_of(f1[0], f1[1]);
                    pa[3] = bf16x2_of(f1[2], f1[3]);
                    pal[0] = bf16x2_of(f0[0] - __uint_as_float(pa[0] << 16),
                                       f0[1] - __uint_as_float(pa[0] & 0xffff0000u));
                    pal[1] = bf16x2_of(f0[2] - __uint_as_float(pa[1] << 16),
                                       f0[3] - __uint_as_float(pa[1] & 0xffff0000u));
                    pal[2] = bf16x2_of(f1[0] - __uint_as_float(pa[2] << 16),
                                       f1[1] - __uint_as_float(pa[2] & 0xffff0000u));
                    pal[3] = bf16x2_of(f1[2] - __uint_as_float(pa[3] << 16),
                                       f1[3] - __uint_as_float(pa[3] & 0xffff0000u));
                }
                uint32_t vh[4][4], vl[4][4];
                #pragma unroll
                for (int jd = 0; jd < 4; jd++) {
                    int row = jp * 16 + (lane & 7) + (((lane >> 3) & 1) << 3);
                    int c = 2 * jd + (lane >> 4);
                    ldsm4t(vh[jd], swz(ss + 16384, row, c));
                    ldsm4t(vl[jd], swz(ss + 24576, row, c));
                }
                #pragma unroll
                for (int nt = 0; nt < 8; nt++)
                    mma16816(oacc[nt], pa, &vh[nt >> 1][(nt & 1) * 2]);
                #pragma unroll
                for (int nt = 0; nt < 8; nt++)
                    mma16816(oacc[nt], pa, &vl[nt >> 1][(nt & 1) * 2]);
                #pragma unroll
                for (int nt = 0; nt < 8; nt++)
                    mma16816(oacc[nt], pal, &vh[nt >> 1][(nt & 1) * 2]);
            }
        }
        __syncthreads();
    }

    float inv0 = 1.0f / l_run[0];
    float inv1 = 1.0f / l_run[1];
    #pragma unroll
    for (int nt = 0; nt < 8; nt++)
        #pragma unroll
        for (int rh = 0; rh < 2; rh++) {
            float iv = rh ? inv1 : inv0;
            float o0 = oacc[nt][rh * 2] * iv;
            float o1 = oacc[nt][rh * 2 + 1] * iv;
            uint32_t h01 = bf16x2_of(o0, o1);
            float e0 = o0 - __uint_as_float(h01 << 16);
            float e1 = o1 - __uint_as_float(h01 & 0xffff0000u);
            size_t token = (size_t)(bT + t0 + wm * 16 + (lane >> 2) + rh * 8);
            size_t idx = (token * CC + h * HD + nt * 8 + (lane & 3) * 2) >> 1;
            oh[idx] = h01;
            ol[idx] = bf16x2_of(e0, e1);
        }
}

// ---------------------------------------------------------------------------
// Launch
// ---------------------------------------------------------------------------
extern "C" void kernel_launch(void* const* d_in, const int* in_sizes, int n_in,
                              void* d_out, int out_size)
{
    const float* x      = (const float*)d_in[0];
    const float* qkv_w  = (const float*)d_in[1];
    const float* qkv_b  = (const float*)d_in[2];
    const float* out_w  = (const float*)d_in[3];
    const float* out_b  = (const float*)d_in[4];
    float* out = (float*)d_out;

    uint32_t *xh, *xl, *w1h, *w1l, *w2h, *w2l, *qh, *ql, *ath, *atl;
    cudaGetSymbolAddress((void**)&xh, g_xh);     cudaGetSymbolAddress((void**)&xl, g_xl);
    cudaGetSymbolAddress((void**)&w1h, g_w1h);   cudaGetSymbolAddress((void**)&w1l, g_w1l);
    cudaGetSymbolAddress((void**)&w2h, g_w2h);   cudaGetSymbolAddress((void**)&w2l, g_w2l);
    cudaGetSymbolAddress((void**)&qh, g_qkvh);   cudaGetSymbolAddress((void**)&ql, g_qkvl);
    cudaGetSymbolAddress((void**)&ath, g_ath);   cudaGetSymbolAddress((void**)&atl, g_atl);

    cudaFuncSetAttribute(gemm_mma<true>,  cudaFuncAttributeMaxDynamicSharedMemorySize, GEMM_DSM);
    cudaFuncSetAttribute(gemm_mma<false>, cudaFuncAttributeMaxDynamicSharedMemorySize, GEMM_DSM);
    cudaFuncSetAttribute(attn_mma, cudaFuncAttributeMaxDynamicSharedMemorySize, ATTN_DSM);

    // 0) split inputs/weights to bf16 hi/lo
    {
        int n4 = MTOK * CC / 4;
        split_bf16<<<n4 / 256, 256>>>((const float4*)x, xh, xl, n4);
        n4 = C3 * CC / 4;
        split_bf16<<<n4 / 256, 256>>>((const float4*)qkv_w, w1h, w1l, n4);
        n4 = CC * CC / 4;
        split_bf16<<<n4 / 256, 256>>>((const float4*)out_w, w2h, w2l, n4);
    }
    // 1) QKV projection -> split bf16 qkv
    {
        dim3 grid(C3 / 64, MTOK / 128);
        gemm_mma<true><<<grid, 256, GEMM_DSM>>>(xh, xl, w1h, w1l, qkv_b,
                                                nullptr, qh, ql, MTOK, C3, CC);
    }
    // 2) Causal flash attention (tensor cores) -> split bf16
    {
        dim3 grid(TT / QTILE, HH, BB);
        attn_mma<<<grid, 256, ATTN_DSM>>>(qh, ql, ath, atl);
    }
    // 3) Output projection -> fp32
    {
        dim3 grid(CC / 64, MTOK / 128);
        gemm_mma<false><<<grid, 256, GEMM_DSM>>>(ath, atl, w2h, w2l, out_b,
                                                 out, nullptr, nullptr, MTOK, CC, CC);
    }
}

// round 6
// speedup vs baseline: 4.7671x; 1.6172x over previous
#include <cuda_runtime.h>
#include <cuda_fp16.h>
#include <cstdint>

// Problem constants
#define BB 4
#define TT 2048
#define CC 1024
#define HH 16
#define HD 64
#define MTOK (BB*TT)        // 8192
#define C3  (3*CC)          // 3072

// Scratch (allocation-guard-safe: __device__ globals). fp16 pairs stored as u32.
__device__ uint32_t g_xf[(size_t)MTOK * CC / 2];
__device__ uint32_t g_w1h[(size_t)C3 * CC / 2], g_w1l[(size_t)C3 * CC / 2];
__device__ uint32_t g_w2h[(size_t)CC * CC / 2], g_w2l[(size_t)CC * CC / 2];
__device__ uint32_t g_qkvf[(size_t)MTOK * C3 / 2];
__device__ uint32_t g_atf[(size_t)MTOK * CC / 2];

// ---------------------------------------------------------------------------
// Helpers
// ---------------------------------------------------------------------------
__device__ __forceinline__ uint32_t smem_u32(const void* p) {
    uint32_t a;
    asm("{ .reg .u64 t; cvta.to.shared.u64 t, %1; cvt.u32.u64 %0, t; }" : "=r"(a) : "l"(p));
    return a;
}
// pack (lo,hi) -> f16x2 with 'lo' in LOW half
__device__ __forceinline__ uint32_t f16x2_of(float lo, float hi) {
    uint32_t r;
    asm("cvt.rn.f16x2.f32 %0, %1, %2;" : "=r"(r) : "f"(hi), "f"(lo));
    return r;
}
__device__ __forceinline__ void cp16(uint32_t s, const void* g) {
    asm volatile("cp.async.cg.shared.global [%0], [%1], 16;" :: "r"(s), "l"(g) : "memory");
}
__device__ __forceinline__ void cpcommit() {
    asm volatile("cp.async.commit_group;" ::: "memory");
}
__device__ __forceinline__ void cpwait0() { asm volatile("cp.async.wait_group 0;" ::: "memory"); }
__device__ __forceinline__ void cpwait1() { asm volatile("cp.async.wait_group 1;" ::: "memory"); }
__device__ __forceinline__ void ldsm4(uint32_t* r, uint32_t a) {
    asm volatile("ldmatrix.sync.aligned.m8n8.x4.shared.b16 {%0,%1,%2,%3}, [%4];"
        : "=r"(r[0]), "=r"(r[1]), "=r"(r[2]), "=r"(r[3]) : "r"(a));
}
__device__ __forceinline__ void ldsm4t(uint32_t* r, uint32_t a) {
    asm volatile("ldmatrix.sync.aligned.m8n8.x4.trans.shared.b16 {%0,%1,%2,%3}, [%4];"
        : "=r"(r[0]), "=r"(r[1]), "=r"(r[2]), "=r"(r[3]) : "r"(a));
}
__device__ __forceinline__ void mma16816(float* c, const uint32_t* a, const uint32_t* b) {
    asm volatile("mma.sync.aligned.m16n8k16.row.col.f32.f16.f16.f32 "
        "{%0,%1,%2,%3}, {%4,%5,%6,%7}, {%8,%9}, {%0,%1,%2,%3};"
        : "+f"(c[0]), "+f"(c[1]), "+f"(c[2]), "+f"(c[3])
        : "r"(a[0]), "r"(a[1]), "r"(a[2]), "r"(a[3]), "r"(b[0]), "r"(b[1]));
}

// ---------------------------------------------------------------------------
// Conversions: fp32 -> fp16 (single) ; fp32 -> fp16 hi/lo split (weights)
// ---------------------------------------------------------------------------
__global__ void cvt_f16(const float4* __restrict__ in, uint32_t* __restrict__ o, int n4)
{
    int i = blockIdx.x * blockDim.x + threadIdx.x;
    if (i >= n4) return;
    float4 f = in[i];
    *(uint2*)&o[2 * i] = make_uint2(f16x2_of(f.x, f.y), f16x2_of(f.z, f.w));
}
__global__ void split_f16(const float4* __restrict__ in, uint32_t* __restrict__ hi,
                          uint32_t* __restrict__ lo, int n4)
{
    int i = blockIdx.x * blockDim.x + threadIdx.x;
    if (i >= n4) return;
    float4 f = in[i];
    __half2 h01 = __floats2half2_rn(f.x, f.y);
    __half2 h23 = __floats2half2_rn(f.z, f.w);
    float2 b01 = __half22float2(h01);
    float2 b23 = __half22float2(h23);
    __half2 l01 = __floats2half2_rn(f.x - b01.x, f.y - b01.y);
    __half2 l23 = __floats2half2_rn(f.z - b23.x, f.w - b23.y);
    *(uint2*)&hi[2 * i] = make_uint2(*(uint32_t*)&h01, *(uint32_t*)&h23);
    *(uint2*)&lo[2 * i] = make_uint2(*(uint32_t*)&l01, *(uint32_t*)&l23);
}

// ---------------------------------------------------------------------------
// GEMM via mma.sync: Out[m][n] = sum_k A[m][k]*W[n][k] + bias[n]
// A single fp16, W split fp16: D = A*Wh + A*Wl (2 passes).
// CTA tile 128x64x32, warp tile 32x32, 8 warps (4M x 2N), 4-stage cp.async.
// Stage = A 8K | Bh 4K | Bl 4K = 16 KB. 64B rows, swizzle chunk ^ ((row>>1)&3).
// OUT_HALF=true writes fp16 (u32 pairs); else fp32.
// ---------------------------------------------------------------------------
#define BK 32
#define STAGES 4
#define SBYTES 16384
#define GEMM_DSM (STAGES * SBYTES + 1024)

__device__ __forceinline__ uint32_t swz4(uint32_t base, int row, int c) {
    return base + (uint32_t)(row * 64) + (uint32_t)((c ^ ((row >> 1) & 3)) << 4);
}

template<bool OUT_HALF>
__global__ void __launch_bounds__(256, 2)
gemm_mma(const uint32_t* __restrict__ A2, const uint32_t* __restrict__ Bh2,
         const uint32_t* __restrict__ Bl2, const float* __restrict__ bias,
         float* __restrict__ OutF, uint32_t* __restrict__ OutH,
         int M, int N, int K)
{
    extern __shared__ char dsm[];
    const uint32_t sbase = (smem_u32(dsm) + 1023u) & ~1023u;

    const int tid  = threadIdx.x;
    const int lane = tid & 31;
    const int warp = tid >> 5;
    const int wm = warp & 3;
    const int wn = warp >> 2;
    const int m0 = blockIdx.y * 128;
    const int n0 = blockIdx.x * 64;

    // A loader: r = tid>>1 (0..127), chunks (tid&1)*2 + {0,1}
    const int alr  = tid >> 1;
    const int alkc = (tid & 1) * 2;
    // B loader: r = tid>>2 (0..63), chunk tid&3, both h and l
    const int blr  = tid >> 2;
    const int blkc = tid & 3;

    const char* pA  = (const char*)A2  + ((size_t)(m0 + alr) * K) * 2;
    const char* pBh = (const char*)Bh2 + ((size_t)(n0 + blr) * K) * 2;
    const char* pBl = (const char*)Bl2 + ((size_t)(n0 + blr) * K) * 2;

    float acc[2][4][4] = {};
    const int NKI = K / BK;

    auto load_stage = [&](int s, int it) {
        const uint32_t ss = sbase + s * SBYTES;
        const int gko = it * BK * 2;
        #pragma unroll
        for (int i = 0; i < 2; i++) {
            const int kc = alkc + i;
            cp16(swz4(ss, alr, kc), pA + gko + kc * 16);
        }
        {
            const uint32_t so = swz4(0, blr, blkc);
            cp16(ss + 8192  + so, pBh + gko + blkc * 16);
            cp16(ss + 12288 + so, pBl + gko + blkc * 16);
        }
    };

    auto compute_stage = [&](int s) {
        const uint32_t ss = sbase + s * SBYTES;
        #pragma unroll
        for (int ks = 0; ks < 2; ks++) {
            uint32_t a[2][4];
            #pragma unroll
            for (int mt = 0; mt < 2; mt++) {
                int row = wm * 32 + mt * 16 + (lane & 15);
                int kc  = ks * 2 + (lane >> 4);
                ldsm4(a[mt], swz4(ss, row, kc));
            }
            uint32_t bh[2][4], bl[2][4];
            #pragma unroll
            for (int jj = 0; jj < 2; jj++) {
                int row = wn * 32 + jj * 16 + (lane & 7) + ((lane >> 4) << 3);
                int kc  = ks * 2 + ((lane >> 3) & 1);
                uint32_t so = swz4(0, row, kc);
                ldsm4(bh[jj], ss + 8192  + so);
                ldsm4(bl[jj], ss + 12288 + so);
            }
            #pragma unroll
            for (int mt = 0; mt < 2; mt++)
                #pragma unroll
                for (int nt = 0; nt < 4; nt++)
                    mma16816(acc[mt][nt], a[mt], &bh[nt >> 1][(nt & 1) * 2]);
            #pragma unroll
            for (int mt = 0; mt < 2; mt++)
                #pragma unroll
                for (int nt = 0; nt < 4; nt++)
                    mma16816(acc[mt][nt], a[mt], &bl[nt >> 1][(nt & 1) * 2]);
        }
    };

    #pragma unroll
    for (int s = 0; s < STAGES - 1; s++) { load_stage(s, s); cpcommit(); }

    for (int it = 0; it < NKI; it++) {
        asm volatile("cp.async.wait_group %0;" :: "n"(STAGES - 2) : "memory");
        __syncthreads();
        const int nit = it + STAGES - 1;
        if (nit < NKI) load_stage(nit % STAGES, nit);
        cpcommit();
        compute_stage(it % STAGES);
    }

    const int rr = lane >> 2;
    const int cc = (lane & 3) * 2;
    #pragma unroll
    for (int mt = 0; mt < 2; mt++)
        #pragma unroll
        for (int nt = 0; nt < 4; nt++) {
            const int col = n0 + wn * 32 + nt * 8 + cc;
            const float b0 = bias[col], b1 = bias[col + 1];
            #pragma unroll
            for (int hf = 0; hf < 2; hf++) {
                const int row = m0 + wm * 32 + mt * 16 + rr + hf * 8;
                float v0 = acc[mt][nt][hf * 2 + 0] + b0;
                float v1 = acc[mt][nt][hf * 2 + 1] + b1;
                if (OUT_HALF) {
                    OutH[((size_t)row * N + col) >> 1] = f16x2_of(v0, v1);
                } else {
                    *(float2*)&OutF[(size_t)row * N + col] = make_float2(v0, v1);
                }
            }
        }
}

// ---------------------------------------------------------------------------
// Flash attention (causal), single-pass fp16 mma.sync.
// Grid (T/128, H, B), 256 threads (8 warps; warp w owns q rows w*16..+15).
// smem: Q 16K + 2 stages x (K 8K | V 8K). 128B rows, swz chunk ^ (row&7).
// ---------------------------------------------------------------------------
#define QTILE 128
#define KTILE 64
#define ASTAGE 16384
#define ATTN_DSM (16384 + 2 * ASTAGE + 1024)

__device__ __forceinline__ uint32_t swz(uint32_t base, int row, int chunk) {
    return base + (uint32_t)(row * 128) + (uint32_t)((chunk ^ (row & 7)) << 4);
}

__global__ void __launch_bounds__(256, 1)
attn_mma(const uint32_t* __restrict__ qkvf, uint32_t* __restrict__ of)
{
    extern __shared__ char dsm[];
    const uint32_t sb = (smem_u32(dsm) + 1023u) & ~1023u;
    const uint32_t sQ = sb, sStage = sb + 16384;

    const int tid = threadIdx.x;
    const int lane = tid & 31;
    const int wm = tid >> 5;
    const int qt = blockIdx.x;
    const int h  = blockIdx.y;
    const int b  = blockIdx.z;
    const int t0 = qt * QTILE;
    const int bT = b * TT;

    const char* pf = (const char*)qkvf;
    const int nkt = 2 * (qt + 1);

    auto load_q = [&]() {
        #pragma unroll
        for (int i = 0; i < 4; i++) {
            int idx = i * 256 + tid;
            int r = idx >> 3, c = idx & 7;
            cp16(swz(sQ, r, c), pf + ((size_t)(bT + t0 + r) * C3 + h * HD) * 2 + c * 16);
        }
    };
    auto load_kv = [&](int kt, int buf) {
        const uint32_t ss = sStage + buf * ASTAGE;
        int r = tid >> 2;
        int cbase = (tid & 3) * 2;
        size_t rowg = (size_t)(bT + kt * KTILE + r) * C3;
        size_t kb = (rowg + CC + h * HD) * 2;
        size_t vb = (rowg + 2 * CC + h * HD) * 2;
        #pragma unroll
        for (int j = 0; j < 2; j++) {
            int c = cbase + j;
            cp16(swz(ss,        r, c), pf + kb + c * 16);
            cp16(swz(ss + 8192, r, c), pf + vb + c * 16);
        }
    };

    load_q();
    load_kv(0, 0);
    cpcommit();

    uint32_t qf[4][4];
    float oacc[8][4] = {};
    float m_prev[2] = {-1e30f, -1e30f};
    float l_run[2] = {0.0f, 0.0f};
    const float scale = 0.125f;
    bool qload = false;

    for (int kt = 0; kt < nkt; kt++) {
        if (kt + 1 < nkt) { load_kv(kt + 1, (kt + 1) & 1); cpcommit(); cpwait1(); }
        else cpwait0();
        __syncthreads();

        if (!qload) {
            qload = true;
            #pragma unroll
            for (int ks = 0; ks < 4; ks++) {
                int row = wm * 16 + (lane & 15);
                int c = ks * 2 + (lane >> 4);
                ldsm4(qf[ks], swz(sQ, row, c));
            }
        }

        const uint32_t ss = sStage + (kt & 1) * ASTAGE;
        const bool doCompute = (kt * KTILE) <= (t0 + wm * 16 + 15);
        if (doCompute) {
            // ---- S = Q K^T (1 pass) ----
            float sacc[8][4] = {};
            #pragma unroll
            for (int ks = 0; ks < 4; ks++) {
                uint32_t bh[4][4];
                #pragma unroll
                for (int jj = 0; jj < 4; jj++) {
                    int row = jj * 16 + (lane & 7) + ((lane >> 4) << 3);
                    int c = ks * 2 + ((lane >> 3) & 1);
                    ldsm4(bh[jj], swz(ss, row, c));
                }
                #pragma unroll
                for (int nt = 0; nt < 8; nt++)
                    mma16816(sacc[nt], qf[ks], &bh[nt >> 1][(nt & 1) * 2]);
            }

            // ---- scale + causal mask ----
            const bool anyMask = (kt * KTILE + KTILE - 1) > (t0 + wm * 16);
            #pragma unroll
            for (int nt = 0; nt < 8; nt++)
                #pragma unroll
                for (int e = 0; e < 4; e++) {
                    float v = sacc[nt][e] * scale;
                    if (anyMask) {
                        int rg = t0 + wm * 16 + (lane >> 2) + (e >> 1) * 8;
                        int cg = kt * KTILE + nt * 8 + (lane & 3) * 2 + (e & 1);
                        if (cg > rg) v = -1e30f;
                    }
                    sacc[nt][e] = v;
                }

            // ---- online softmax ----
            #pragma unroll
            for (int rh = 0; rh < 2; rh++) {
                float mloc = -1e30f;
                #pragma unroll
                for (int nt = 0; nt < 8; nt++)
                    mloc = fmaxf(mloc, fmaxf(sacc[nt][rh * 2], sacc[nt][rh * 2 + 1]));
                mloc = fmaxf(mloc, __shfl_xor_sync(0xffffffffu, mloc, 1));
                mloc = fmaxf(mloc, __shfl_xor_sync(0xffffffffu, mloc, 2));
                float mnew = fmaxf(m_prev[rh], mloc);
                float corr = __expf(m_prev[rh] - mnew);
                m_prev[rh] = mnew;
                float ls = 0.0f;
                #pragma unroll
                for (int nt = 0; nt < 8; nt++) {
                    float p0 = __expf(sacc[nt][rh * 2]     - mnew);
                    float p1 = __expf(sacc[nt][rh * 2 + 1] - mnew);
                    sacc[nt][rh * 2] = p0; sacc[nt][rh * 2 + 1] = p1;
                    ls += p0 + p1;
                }
                ls += __shfl_xor_sync(0xffffffffu, ls, 1);
                ls += __shfl_xor_sync(0xffffffffu, ls, 2);
                l_run[rh] = l_run[rh] * corr + ls;
                #pragma unroll
                for (int nt = 0; nt < 8; nt++) {
                    oacc[nt][rh * 2]     *= corr;
                    oacc[nt][rh * 2 + 1] *= corr;
                }
            }

            // ---- O += P V (1 pass) ----
            #pragma unroll
            for (int jp = 0; jp < 4; jp++) {
                uint32_t pa[4];
                {
                    const float* f0 = sacc[2 * jp];
                    const float* f1 = sacc[2 * jp + 1];
                    pa[0] = f16x2_of(f0[0], f0[1]);
                    pa[1] = f16x2_of(f0[2], f0[3]);
                    pa[2] = f16x2_of(f1[0], f1[1]);
                    pa[3] = f16x2_of(f1[2], f1[3]);
                }
                uint32_t vh[4][4];
                #pragma unroll
                for (int jd = 0; jd < 4; jd++) {
                    int row = jp * 16 + (lane & 7) + (((lane >> 3) & 1) << 3);
                    int c = 2 * jd + (lane >> 4);
                    ldsm4t(vh[jd], swz(ss + 8192, row, c));
                }
                #pragma unroll
                for (int nt = 0; nt < 8; nt++)
                    mma16816(oacc[nt], pa, &vh[nt >> 1][(nt & 1) * 2]);
            }
        }
        __syncthreads();
    }

    // ---- epilogue: normalize, fp16, store ----
    float inv0 = 1.0f / l_run[0];
    float inv1 = 1.0f / l_run[1];
    #pragma unroll
    for (int nt = 0; nt < 8; nt++)
        #pragma unroll
        for (int rh = 0; rh < 2; rh++) {
            float iv = rh ? inv1 : inv0;
            float o0 = oacc[nt][rh * 2] * iv;
            float o1 = oacc[nt][rh * 2 + 1] * iv;
            size_t token = (size_t)(bT + t0 + wm * 16 + (lane >> 2) + rh * 8);
            of[(token * CC + h * HD + nt * 8 + (lane & 3) * 2) >> 1] = f16x2_of(o0, o1);
        }
}

// ---------------------------------------------------------------------------
// Launch
// ---------------------------------------------------------------------------
extern "C" void kernel_launch(void* const* d_in, const int* in_sizes, int n_in,
                              void* d_out, int out_size)
{
    const float* x      = (const float*)d_in[0];
    const float* qkv_w  = (const float*)d_in[1];
    const float* qkv_b  = (const float*)d_in[2];
    const float* out_w  = (const float*)d_in[3];
    const float* out_b  = (const float*)d_in[4];
    float* out = (float*)d_out;

    uint32_t *xf, *w1h, *w1l, *w2h, *w2l, *qf, *atf;
    cudaGetSymbolAddress((void**)&xf, g_xf);
    cudaGetSymbolAddress((void**)&w1h, g_w1h); cudaGetSymbolAddress((void**)&w1l, g_w1l);
    cudaGetSymbolAddress((void**)&w2h, g_w2h); cudaGetSymbolAddress((void**)&w2l, g_w2l);
    cudaGetSymbolAddress((void**)&qf, g_qkvf);
    cudaGetSymbolAddress((void**)&atf, g_atf);

    cudaFuncSetAttribute(gemm_mma<true>,  cudaFuncAttributeMaxDynamicSharedMemorySize, GEMM_DSM);
    cudaFuncSetAttribute(gemm_mma<false>, cudaFuncAttributeMaxDynamicSharedMemorySize, GEMM_DSM);
    cudaFuncSetAttribute(attn_mma, cudaFuncAttributeMaxDynamicSharedMemorySize, ATTN_DSM);

    // 0) convert x to fp16; split weights to fp16 hi/lo
    {
        int n4 = MTOK * CC / 4;
        cvt_f16<<<n4 / 256, 256>>>((const float4*)x, xf, n4);
        n4 = C3 * CC / 4;
        split_f16<<<n4 / 256, 256>>>((const float4*)qkv_w, w1h, w1l, n4);
        n4 = CC * CC / 4;
        split_f16<<<n4 / 256, 256>>>((const float4*)out_w, w2h, w2l, n4);
    }
    // 1) QKV projection -> fp16 qkv
    {
        dim3 grid(C3 / 64, MTOK / 128);
        gemm_mma<true><<<grid, 256, GEMM_DSM>>>(xf, w1h, w1l, qkv_b,
                                                nullptr, qf, MTOK, C3, CC);
    }
    // 2) Causal flash attention -> fp16
    {
        dim3 grid(TT / QTILE, HH, BB);
        attn_mma<<<grid, 256, ATTN_DSM>>>(qf, atf);
    }
    // 3) Output projection -> fp32
    {
        dim3 grid(CC / 64, MTOK / 128);
        gemm_mma<false><<<grid, 256, GEMM_DSM>>>(atf, w2h, w2l, out_b,
                                                 out, nullptr, MTOK, CC, CC);
    }
}

// round 7
// speedup vs baseline: 6.2064x; 1.3019x over previous
#include <cuda_runtime.h>
#include <cuda_fp16.h>
#include <cstdint>

// Problem constants
#define BB 4
#define TT 2048
#define CC 1024
#define HH 16
#define HD 64
#define MTOK (BB*TT)        // 8192
#define C3  (3*CC)          // 3072

// Scratch (allocation-guard-safe: __device__ globals). fp16 pairs stored as u32.
__device__ uint32_t g_xf[(size_t)MTOK * CC / 2];
__device__ uint32_t g_w1f[(size_t)C3 * CC / 2];
__device__ uint32_t g_w2f[(size_t)CC * CC / 2];
__device__ uint32_t g_qkvf[(size_t)MTOK * C3 / 2];
__device__ uint32_t g_atf[(size_t)MTOK * CC / 2];

// ---------------------------------------------------------------------------
// Helpers
// ---------------------------------------------------------------------------
__device__ __forceinline__ uint32_t smem_u32(const void* p) {
    uint32_t a;
    asm("{ .reg .u64 t; cvta.to.shared.u64 t, %1; cvt.u32.u64 %0, t; }" : "=r"(a) : "l"(p));
    return a;
}
// pack (lo,hi) -> f16x2 with 'lo' in LOW half
__device__ __forceinline__ uint32_t f16x2_of(float lo, float hi) {
    uint32_t r;
    asm("cvt.rn.f16x2.f32 %0, %1, %2;" : "=r"(r) : "f"(hi), "f"(lo));
    return r;
}
__device__ __forceinline__ void cp16(uint32_t s, const void* g) {
    asm volatile("cp.async.cg.shared.global [%0], [%1], 16;" :: "r"(s), "l"(g) : "memory");
}
__device__ __forceinline__ void cpcommit() {
    asm volatile("cp.async.commit_group;" ::: "memory");
}
__device__ __forceinline__ void cpwait0() { asm volatile("cp.async.wait_group 0;" ::: "memory"); }
__device__ __forceinline__ void cpwait1() { asm volatile("cp.async.wait_group 1;" ::: "memory"); }
__device__ __forceinline__ void ldsm4(uint32_t* r, uint32_t a) {
    asm volatile("ldmatrix.sync.aligned.m8n8.x4.shared.b16 {%0,%1,%2,%3}, [%4];"
        : "=r"(r[0]), "=r"(r[1]), "=r"(r[2]), "=r"(r[3]) : "r"(a));
}
__device__ __forceinline__ void ldsm4t(uint32_t* r, uint32_t a) {
    asm volatile("ldmatrix.sync.aligned.m8n8.x4.trans.shared.b16 {%0,%1,%2,%3}, [%4];"
        : "=r"(r[0]), "=r"(r[1]), "=r"(r[2]), "=r"(r[3]) : "r"(a));
}
__device__ __forceinline__ void mma16816(float* c, const uint32_t* a, const uint32_t* b) {
    asm volatile("mma.sync.aligned.m16n8k16.row.col.f32.f16.f16.f32 "
        "{%0,%1,%2,%3}, {%4,%5,%6,%7}, {%8,%9}, {%0,%1,%2,%3};"
        : "+f"(c[0]), "+f"(c[1]), "+f"(c[2]), "+f"(c[3])
        : "r"(a[0]), "r"(a[1]), "r"(a[2]), "r"(a[3]), "r"(b[0]), "r"(b[1]));
}

// ---------------------------------------------------------------------------
// Conversion: fp32 -> fp16
// ---------------------------------------------------------------------------
__global__ void cvt_f16(const float4* __restrict__ in, uint32_t* __restrict__ o, int n4)
{
    int i = blockIdx.x * blockDim.x + threadIdx.x;
    if (i >= n4) return;
    float4 f = in[i];
    *(uint2*)&o[2 * i] = make_uint2(f16x2_of(f.x, f.y), f16x2_of(f.z, f.w));
}

// ---------------------------------------------------------------------------
// GEMM via mma.sync (single-pass fp16):
//   Out[m][n] = sum_k A[m][k]*W[n][k] + bias[n]
// CTA tile 128x64x32, warp tile 32x32, 8 warps (4M x 2N), 4-stage cp.async.
// Stage = A 8K | B 4K = 12 KB. 64B rows, swizzle chunk ^ ((row>>1)&3).
// OUT_HALF=true writes fp16 (u32 pairs); else fp32.
// ---------------------------------------------------------------------------
#define BK 32
#define STAGES 4
#define SBYTES 12288
#define GEMM_DSM (STAGES * SBYTES + 1024)

__device__ __forceinline__ uint32_t swz4(uint32_t base, int row, int c) {
    return base + (uint32_t)(row * 64) + (uint32_t)((c ^ ((row >> 1) & 3)) << 4);
}

template<bool OUT_HALF>
__global__ void __launch_bounds__(256, 2)
gemm_mma(const uint32_t* __restrict__ A2, const uint32_t* __restrict__ B2,
         const float* __restrict__ bias,
         float* __restrict__ OutF, uint32_t* __restrict__ OutH,
         int M, int N, int K)
{
    extern __shared__ char dsm[];
    const uint32_t sbase = (smem_u32(dsm) + 1023u) & ~1023u;

    const int tid  = threadIdx.x;
    const int lane = tid & 31;
    const int warp = tid >> 5;
    const int wm = warp & 3;
    const int wn = warp >> 2;
    const int m0 = blockIdx.y * 128;
    const int n0 = blockIdx.x * 64;

    // A loader: r = tid>>1 (0..127), chunks (tid&1)*2 + {0,1}
    const int alr  = tid >> 1;
    const int alkc = (tid & 1) * 2;
    // B loader: first 256 lanes cover 64 rows x 4 chunks
    const int blr  = tid >> 2;
    const int blkc = tid & 3;

    const char* pA = (const char*)A2 + ((size_t)(m0 + alr) * K) * 2;
    const char* pB = (const char*)B2 + ((size_t)(n0 + blr) * K) * 2;

    float acc[2][4][4] = {};
    const int NKI = K / BK;

    auto load_stage = [&](int s, int it) {
        const uint32_t ss = sbase + s * SBYTES;
        const int gko = it * BK * 2;
        #pragma unroll
        for (int i = 0; i < 2; i++) {
            const int kc = alkc + i;
            cp16(swz4(ss, alr, kc), pA + gko + kc * 16);
        }
        cp16(ss + 8192 + swz4(0, blr, blkc), pB + gko + blkc * 16);
    };

    auto compute_stage = [&](int s) {
        const uint32_t ss = sbase + s * SBYTES;
        #pragma unroll
        for (int ks = 0; ks < 2; ks++) {
            uint32_t a[2][4];
            #pragma unroll
            for (int mt = 0; mt < 2; mt++) {
                int row = wm * 32 + mt * 16 + (lane & 15);
                int kc  = ks * 2 + (lane >> 4);
                ldsm4(a[mt], swz4(ss, row, kc));
            }
            uint32_t b[2][4];
            #pragma unroll
            for (int jj = 0; jj < 2; jj++) {
                int row = wn * 32 + jj * 16 + (lane & 7) + ((lane >> 4) << 3);
                int kc  = ks * 2 + ((lane >> 3) & 1);
                ldsm4(b[jj], ss + 8192 + swz4(0, row, kc));
            }
            #pragma unroll
            for (int mt = 0; mt < 2; mt++)
                #pragma unroll
                for (int nt = 0; nt < 4; nt++)
                    mma16816(acc[mt][nt], a[mt], &b[nt >> 1][(nt & 1) * 2]);
        }
    };

    #pragma unroll
    for (int s = 0; s < STAGES - 1; s++) { load_stage(s, s); cpcommit(); }

    for (int it = 0; it < NKI; it++) {
        asm volatile("cp.async.wait_group %0;" :: "n"(STAGES - 2) : "memory");
        __syncthreads();
        const int nit = it + STAGES - 1;
        if (nit < NKI) load_stage(nit % STAGES, nit);
        cpcommit();
        compute_stage(it % STAGES);
    }

    const int rr = lane >> 2;
    const int cc = (lane & 3) * 2;
    #pragma unroll
    for (int mt = 0; mt < 2; mt++)
        #pragma unroll
        for (int nt = 0; nt < 4; nt++) {
            const int col = n0 + wn * 32 + nt * 8 + cc;
            const float b0 = bias[col], b1 = bias[col + 1];
            #pragma unroll
            for (int hf = 0; hf < 2; hf++) {
                const int row = m0 + wm * 32 + mt * 16 + rr + hf * 8;
                float v0 = acc[mt][nt][hf * 2 + 0] + b0;
                float v1 = acc[mt][nt][hf * 2 + 1] + b1;
                if (OUT_HALF) {
                    OutH[((size_t)row * N + col) >> 1] = f16x2_of(v0, v1);
                } else {
                    *(float2*)&OutF[(size_t)row * N + col] = make_float2(v0, v1);
                }
            }
        }
}

// ---------------------------------------------------------------------------
// Flash attention (causal), single-pass fp16 mma.sync (unchanged from R6).
// ---------------------------------------------------------------------------
#define QTILE 128
#define KTILE 64
#define ASTAGE 16384
#define ATTN_DSM (16384 + 2 * ASTAGE + 1024)

__device__ __forceinline__ uint32_t swz(uint32_t base, int row, int chunk) {
    return base + (uint32_t)(row * 128) + (uint32_t)((chunk ^ (row & 7)) << 4);
}

__global__ void __launch_bounds__(256, 1)
attn_mma(const uint32_t* __restrict__ qkvf, uint32_t* __restrict__ of)
{
    extern __shared__ char dsm[];
    const uint32_t sb = (smem_u32(dsm) + 1023u) & ~1023u;
    const uint32_t sQ = sb, sStage = sb + 16384;

    const int tid = threadIdx.x;
    const int lane = tid & 31;
    const int wm = tid >> 5;
    const int qt = blockIdx.x;
    const int h  = blockIdx.y;
    const int b  = blockIdx.z;
    const int t0 = qt * QTILE;
    const int bT = b * TT;

    const char* pf = (const char*)qkvf;
    const int nkt = 2 * (qt + 1);

    auto load_q = [&]() {
        #pragma unroll
        for (int i = 0; i < 4; i++) {
            int idx = i * 256 + tid;
            int r = idx >> 3, c = idx & 7;
            cp16(swz(sQ, r, c), pf + ((size_t)(bT + t0 + r) * C3 + h * HD) * 2 + c * 16);
        }
    };
    auto load_kv = [&](int kt, int buf) {
        const uint32_t ss = sStage + buf * ASTAGE;
        int r = tid >> 2;
        int cbase = (tid & 3) * 2;
        size_t rowg = (size_t)(bT + kt * KTILE + r) * C3;
        size_t kb = (rowg + CC + h * HD) * 2;
        size_t vb = (rowg + 2 * CC + h * HD) * 2;
        #pragma unroll
        for (int j = 0; j < 2; j++) {
            int c = cbase + j;
            cp16(swz(ss,        r, c), pf + kb + c * 16);
            cp16(swz(ss + 8192, r, c), pf + vb + c * 16);
        }
    };

    load_q();
    load_kv(0, 0);
    cpcommit();

    uint32_t qf[4][4];
    float oacc[8][4] = {};
    float m_prev[2] = {-1e30f, -1e30f};
    float l_run[2] = {0.0f, 0.0f};
    const float scale = 0.125f;
    bool qload = false;

    for (int kt = 0; kt < nkt; kt++) {
        if (kt + 1 < nkt) { load_kv(kt + 1, (kt + 1) & 1); cpcommit(); cpwait1(); }
        else cpwait0();
        __syncthreads();

        if (!qload) {
            qload = true;
            #pragma unroll
            for (int ks = 0; ks < 4; ks++) {
                int row = wm * 16 + (lane & 15);
                int c = ks * 2 + (lane >> 4);
                ldsm4(qf[ks], swz(sQ, row, c));
            }
        }

        const uint32_t ss = sStage + (kt & 1) * ASTAGE;
        const bool doCompute = (kt * KTILE) <= (t0 + wm * 16 + 15);
        if (doCompute) {
            // ---- S = Q K^T (1 pass) ----
            float sacc[8][4] = {};
            #pragma unroll
            for (int ks = 0; ks < 4; ks++) {
                uint32_t bh[4][4];
                #pragma unroll
                for (int jj = 0; jj < 4; jj++) {
                    int row = jj * 16 + (lane & 7) + ((lane >> 4) << 3);
                    int c = ks * 2 + ((lane >> 3) & 1);
                    ldsm4(bh[jj], swz(ss, row, c));
                }
                #pragma unroll
                for (int nt = 0; nt < 8; nt++)
                    mma16816(sacc[nt], qf[ks], &bh[nt >> 1][(nt & 1) * 2]);
            }

            // ---- scale + causal mask ----
            const bool anyMask = (kt * KTILE + KTILE - 1) > (t0 + wm * 16);
            #pragma unroll
            for (int nt = 0; nt < 8; nt++)
                #pragma unroll
                for (int e = 0; e < 4; e++) {
                    float v = sacc[nt][e] * scale;
                    if (anyMask) {
                        int rg = t0 + wm * 16 + (lane >> 2) + (e >> 1) * 8;
                        int cg = kt * KTILE + nt * 8 + (lane & 3) * 2 + (e & 1);
                        if (cg > rg) v = -1e30f;
                    }
                    sacc[nt][e] = v;
                }

            // ---- online softmax ----
            #pragma unroll
            for (int rh = 0; rh < 2; rh++) {
                float mloc = -1e30f;
                #pragma unroll
                for (int nt = 0; nt < 8; nt++)
                    mloc = fmaxf(mloc, fmaxf(sacc[nt][rh * 2], sacc[nt][rh * 2 + 1]));
                mloc = fmaxf(mloc, __shfl_xor_sync(0xffffffffu, mloc, 1));
                mloc = fmaxf(mloc, __shfl_xor_sync(0xffffffffu, mloc, 2));
                float mnew = fmaxf(m_prev[rh], mloc);
                float corr = __expf(m_prev[rh] - mnew);
                m_prev[rh] = mnew;
                float ls = 0.0f;
                #pragma unroll
                for (int nt = 0; nt < 8; nt++) {
                    float p0 = __expf(sacc[nt][rh * 2]     - mnew);
                    float p1 = __expf(sacc[nt][rh * 2 + 1] - mnew);
                    sacc[nt][rh * 2] = p0; sacc[nt][rh * 2 + 1] = p1;
                    ls += p0 + p1;
                }
                ls += __shfl_xor_sync(0xffffffffu, ls, 1);
                ls += __shfl_xor_sync(0xffffffffu, ls, 2);
                l_run[rh] = l_run[rh] * corr + ls;
                #pragma unroll
                for (int nt = 0; nt < 8; nt++) {
                    oacc[nt][rh * 2]     *= corr;
                    oacc[nt][rh * 2 + 1] *= corr;
                }
            }

            // ---- O += P V (1 pass) ----
            #pragma unroll
            for (int jp = 0; jp < 4; jp++) {
                uint32_t pa[4];
                {
                    const float* f0 = sacc[2 * jp];
                    const float* f1 = sacc[2 * jp + 1];
                    pa[0] = f16x2_of(f0[0], f0[1]);
                    pa[1] = f16x2_of(f0[2], f0[3]);
                    pa[2] = f16x2_of(f1[0], f1[1]);
                    pa[3] = f16x2_of(f1[2], f1[3]);
                }
                uint32_t vh[4][4];
                #pragma unroll
                for (int jd = 0; jd < 4; jd++) {
                    int row = jp * 16 + (lane & 7) + (((lane >> 3) & 1) << 3);
                    int c = 2 * jd + (lane >> 4);
                    ldsm4t(vh[jd], swz(ss + 8192, row, c));
                }
                #pragma unroll
                for (int nt = 0; nt < 8; nt++)
                    mma16816(oacc[nt], pa, &vh[nt >> 1][(nt & 1) * 2]);
            }
        }
        __syncthreads();
    }

    // ---- epilogue: normalize, fp16, store ----
    float inv0 = 1.0f / l_run[0];
    float inv1 = 1.0f / l_run[1];
    #pragma unroll
    for (int nt = 0; nt < 8; nt++)
        #pragma unroll
        for (int rh = 0; rh < 2; rh++) {
            float iv = rh ? inv1 : inv0;
            float o0 = oacc[nt][rh * 2] * iv;
            float o1 = oacc[nt][rh * 2 + 1] * iv;
            size_t token = (size_t)(bT + t0 + wm * 16 + (lane >> 2) + rh * 8);
            of[(token * CC + h * HD + nt * 8 + (lane & 3) * 2) >> 1] = f16x2_of(o0, o1);
        }
}

// ---------------------------------------------------------------------------
// Launch
// ---------------------------------------------------------------------------
extern "C" void kernel_launch(void* const* d_in, const int* in_sizes, int n_in,
                              void* d_out, int out_size)
{
    const float* x      = (const float*)d_in[0];
    const float* qkv_w  = (const float*)d_in[1];
    const float* qkv_b  = (const float*)d_in[2];
    const float* out_w  = (const float*)d_in[3];
    const float* out_b  = (const float*)d_in[4];
    float* out = (float*)d_out;

    uint32_t *xf, *w1f, *w2f, *qf, *atf;
    cudaGetSymbolAddress((void**)&xf, g_xf);
    cudaGetSymbolAddress((void**)&w1f, g_w1f);
    cudaGetSymbolAddress((void**)&w2f, g_w2f);
    cudaGetSymbolAddress((void**)&qf, g_qkvf);
    cudaGetSymbolAddress((void**)&atf, g_atf);

    cudaFuncSetAttribute(gemm_mma<true>,  cudaFuncAttributeMaxDynamicSharedMemorySize, GEMM_DSM);
    cudaFuncSetAttribute(gemm_mma<false>, cudaFuncAttributeMaxDynamicSharedMemorySize, GEMM_DSM);
    cudaFuncSetAttribute(attn_mma, cudaFuncAttributeMaxDynamicSharedMemorySize, ATTN_DSM);

    // 0) convert x and weights to fp16
    {
        int n4 = MTOK * CC / 4;
        cvt_f16<<<n4 / 256, 256>>>((const float4*)x, xf, n4);
        n4 = C3 * CC / 4;
        cvt_f16<<<n4 / 256, 256>>>((const float4*)qkv_w, w1f, n4);
        n4 = CC * CC / 4;
        cvt_f16<<<n4 / 256, 256>>>((const float4*)out_w, w2f, n4);
    }
    // 1) QKV projection -> fp16 qkv
    {
        dim3 grid(C3 / 64, MTOK / 128);
        gemm_mma<true><<<grid, 256, GEMM_DSM>>>(xf, w1f, qkv_b, nullptr, qf, MTOK, C3, CC);
    }
    // 2) Causal flash attention -> fp16
    {
        dim3 grid(TT / QTILE, HH, BB);
        attn_mma<<<grid, 256, ATTN_DSM>>>(qf, atf);
    }
    // 3) Output projection -> fp32
    {
        dim3 grid(CC / 64, MTOK / 128);
        gemm_mma<false><<<grid, 256, GEMM_DSM>>>(atf, w2f, out_b, out, nullptr, MTOK, CC, CC);
    }
}

// round 8
// speedup vs baseline: 7.0552x; 1.1368x over previous
#include <cuda_runtime.h>
#include <cuda_fp16.h>
#include <cstdint>

// Problem constants
#define BB 4
#define TT 2048
#define CC 1024
#define HH 16
#define HD 64
#define MTOK (BB*TT)        // 8192
#define C3  (3*CC)          // 3072

// Scratch (allocation-guard-safe: __device__ globals). fp16 pairs stored as u32.
__device__ uint32_t g_xf[(size_t)MTOK * CC / 2];
__device__ uint32_t g_w1f[(size_t)C3 * CC / 2];
__device__ uint32_t g_w2f[(size_t)CC * CC / 2];
__device__ uint32_t g_qkvf[(size_t)MTOK * C3 / 2];
__device__ uint32_t g_atf[(size_t)MTOK * CC / 2];

// ---------------------------------------------------------------------------
// Helpers
// ---------------------------------------------------------------------------
__device__ __forceinline__ uint32_t smem_u32(const void* p) {
    uint32_t a;
    asm("{ .reg .u64 t; cvta.to.shared.u64 t, %1; cvt.u32.u64 %0, t; }" : "=r"(a) : "l"(p));
    return a;
}
// pack (lo,hi) -> f16x2 with 'lo' in LOW half
__device__ __forceinline__ uint32_t f16x2_of(float lo, float hi) {
    uint32_t r;
    asm("cvt.rn.f16x2.f32 %0, %1, %2;" : "=r"(r) : "f"(hi), "f"(lo));
    return r;
}
__device__ __forceinline__ void cp16(uint32_t s, const void* g) {
    asm volatile("cp.async.cg.shared.global [%0], [%1], 16;" :: "r"(s), "l"(g) : "memory");
}
__device__ __forceinline__ void cpcommit() {
    asm volatile("cp.async.commit_group;" ::: "memory");
}
__device__ __forceinline__ void cpwait0() { asm volatile("cp.async.wait_group 0;" ::: "memory"); }
__device__ __forceinline__ void cpwait1() { asm volatile("cp.async.wait_group 1;" ::: "memory"); }
__device__ __forceinline__ void ldsm4(uint32_t* r, uint32_t a) {
    asm volatile("ldmatrix.sync.aligned.m8n8.x4.shared.b16 {%0,%1,%2,%3}, [%4];"
        : "=r"(r[0]), "=r"(r[1]), "=r"(r[2]), "=r"(r[3]) : "r"(a));
}
__device__ __forceinline__ void ldsm4t(uint32_t* r, uint32_t a) {
    asm volatile("ldmatrix.sync.aligned.m8n8.x4.trans.shared.b16 {%0,%1,%2,%3}, [%4];"
        : "=r"(r[0]), "=r"(r[1]), "=r"(r[2]), "=r"(r[3]) : "r"(a));
}
__device__ __forceinline__ void mma16816(float* c, const uint32_t* a, const uint32_t* b) {
    asm volatile("mma.sync.aligned.m16n8k16.row.col.f32.f16.f16.f32 "
        "{%0,%1,%2,%3}, {%4,%5,%6,%7}, {%8,%9}, {%0,%1,%2,%3};"
        : "+f"(c[0]), "+f"(c[1]), "+f"(c[2]), "+f"(c[3])
        : "r"(a[0]), "r"(a[1]), "r"(a[2]), "r"(a[3]), "r"(b[0]), "r"(b[1]));
}

// 128B-row swizzle: 8 chunks of 16B, chunk ^ (row & 7)
__device__ __forceinline__ uint32_t swz(uint32_t base, int row, int chunk) {
    return base + (uint32_t)(row * 128) + (uint32_t)((chunk ^ (row & 7)) << 4);
}

// ---------------------------------------------------------------------------
// Conversion: fp32 -> fp16
// ---------------------------------------------------------------------------
__global__ void cvt_f16(const float4* __restrict__ in, uint32_t* __restrict__ o, int n4)
{
    int i = blockIdx.x * blockDim.x + threadIdx.x;
    if (i >= n4) return;
    float4 f = in[i];
    *(uint2*)&o[2 * i] = make_uint2(f16x2_of(f.x, f.y), f16x2_of(f.z, f.w));
}

// ---------------------------------------------------------------------------
// GEMM via mma.sync (single-pass fp16), BK=64:
//   Out[m][n] = sum_k A[m][k]*W[n][k] + bias[n]
// CTA tile 128x64x64, warp tile 32x32, 8 warps (4M x 2N), 3-stage cp.async.
// Stage = A 16K | B 8K = 24 KB. 128B rows, swizzle chunk ^ (row&7).
// OUT_HALF=true writes fp16 (u32 pairs); else fp32.
// ---------------------------------------------------------------------------
#define BK 64
#define STAGES 3
#define SBYTES 24576
#define GEMM_DSM (STAGES * SBYTES + 1024)

template<bool OUT_HALF>
__global__ void __launch_bounds__(256, 2)
gemm_mma(const uint32_t* __restrict__ A2, const uint32_t* __restrict__ B2,
         const float* __restrict__ bias,
         float* __restrict__ OutF, uint32_t* __restrict__ OutH,
         int M, int N, int K)
{
    extern __shared__ char dsm[];
    const uint32_t sbase = (smem_u32(dsm) + 1023u) & ~1023u;

    const int tid  = threadIdx.x;
    const int lane = tid & 31;
    const int warp = tid >> 5;
    const int wm = warp & 3;
    const int wn = warp >> 2;
    const int m0 = blockIdx.y * 128;
    const int n0 = blockIdx.x * 64;

    // loaders: rows of 128B = 8 chunks; idx = i*256 + tid -> r = idx>>3, c = idx&7
    const int lr = tid >> 3;      // row step base (16 rows per 256/16.. actually idx>>3)
    const int lc = tid & 7;

    const char* pA = (const char*)A2 + (size_t)m0 * K * 2;
    const char* pB = (const char*)B2 + (size_t)n0 * K * 2;

    float acc[2][4][4] = {};
    const int NKI = K / BK;

    auto load_stage = [&](int s, int it) {
        const uint32_t ss = sbase + s * SBYTES;
        const int gko = it * BK * 2;     // byte offset along K
        #pragma unroll
        for (int i = 0; i < 4; i++) {    // A: 128 rows x 8 chunks
            int r = lr + i * 32;
            cp16(swz(ss, r, lc), pA + (size_t)r * K * 2 + gko + lc * 16);
        }
        #pragma unroll
        for (int i = 0; i < 2; i++) {    // B: 64 rows x 8 chunks
            int r = lr + i * 32;
            cp16(swz(ss + 16384, r, lc), pB + (size_t)r * K * 2 + gko + lc * 16);
        }
    };

    auto compute_stage = [&](int s) {
        const uint32_t ss = sbase + s * SBYTES;
        #pragma unroll
        for (int ks = 0; ks < 4; ks++) {
            uint32_t a[2][4];
            #pragma unroll
            for (int mt = 0; mt < 2; mt++) {
                int row = wm * 32 + mt * 16 + (lane & 15);
                int kc  = ks * 2 + (lane >> 4);
                ldsm4(a[mt], swz(ss, row, kc));
            }
            uint32_t b[2][4];
            #pragma unroll
            for (int jj = 0; jj < 2; jj++) {
                int row = wn * 32 + jj * 16 + (lane & 7) + ((lane >> 4) << 3);
                int kc  = ks * 2 + ((lane >> 3) & 1);
                ldsm4(b[jj], swz(ss + 16384, row, kc));
            }
            #pragma unroll
            for (int mt = 0; mt < 2; mt++)
                #pragma unroll
                for (int nt = 0; nt < 4; nt++)
                    mma16816(acc[mt][nt], a[mt], &b[nt >> 1][(nt & 1) * 2]);
        }
    };

    #pragma unroll
    for (int s = 0; s < STAGES - 1; s++) { load_stage(s, s); cpcommit(); }

    for (int it = 0; it < NKI; it++) {
        asm volatile("cp.async.wait_group %0;" :: "n"(STAGES - 2) : "memory");
        __syncthreads();
        const int nit = it + STAGES - 1;
        if (nit < NKI) load_stage(nit % STAGES, nit);
        cpcommit();
        compute_stage(it % STAGES);
    }

    const int rr = lane >> 2;
    const int cc = (lane & 3) * 2;
    #pragma unroll
    for (int mt = 0; mt < 2; mt++)
        #pragma unroll
        for (int nt = 0; nt < 4; nt++) {
            const int col = n0 + wn * 32 + nt * 8 + cc;
            const float b0 = bias[col], b1 = bias[col + 1];
            #pragma unroll
            for (int hf = 0; hf < 2; hf++) {
                const int row = m0 + wm * 32 + mt * 16 + rr + hf * 8;
                float v0 = acc[mt][nt][hf * 2 + 0] + b0;
                float v1 = acc[mt][nt][hf * 2 + 1] + b1;
                if (OUT_HALF) {
                    OutH[((size_t)row * N + col) >> 1] = f16x2_of(v0, v1);
                } else {
                    *(float2*)&OutF[(size_t)row * N + col] = make_float2(v0, v1);
                }
            }
        }
}

// ---------------------------------------------------------------------------
// Flash attention (causal), single-pass fp16 mma.sync (unchanged from R7).
// ---------------------------------------------------------------------------
#define QTILE 128
#define KTILE 64
#define ASTAGE 16384
#define ATTN_DSM (16384 + 2 * ASTAGE + 1024)

__global__ void __launch_bounds__(256, 1)
attn_mma(const uint32_t* __restrict__ qkvf, uint32_t* __restrict__ of)
{
    extern __shared__ char dsm[];
    const uint32_t sb = (smem_u32(dsm) + 1023u) & ~1023u;
    const uint32_t sQ = sb, sStage = sb + 16384;

    const int tid = threadIdx.x;
    const int lane = tid & 31;
    const int wm = tid >> 5;
    const int qt = blockIdx.x;
    const int h  = blockIdx.y;
    const int b  = blockIdx.z;
    const int t0 = qt * QTILE;
    const int bT = b * TT;

    const char* pf = (const char*)qkvf;
    const int nkt = 2 * (qt + 1);

    auto load_q = [&]() {
        #pragma unroll
        for (int i = 0; i < 4; i++) {
            int idx = i * 256 + tid;
            int r = idx >> 3, c = idx & 7;
            cp16(swz(sQ, r, c), pf + ((size_t)(bT + t0 + r) * C3 + h * HD) * 2 + c * 16);
        }
    };
    auto load_kv = [&](int kt, int buf) {
        const uint32_t ss = sStage + buf * ASTAGE;
        int r = tid >> 2;
        int cbase = (tid & 3) * 2;
        size_t rowg = (size_t)(bT + kt * KTILE + r) * C3;
        size_t kb = (rowg + CC + h * HD) * 2;
        size_t vb = (rowg + 2 * CC + h * HD) * 2;
        #pragma unroll
        for (int j = 0; j < 2; j++) {
            int c = cbase + j;
            cp16(swz(ss,        r, c), pf + kb + c * 16);
            cp16(swz(ss + 8192, r, c), pf + vb + c * 16);
        }
    };

    load_q();
    load_kv(0, 0);
    cpcommit();

    uint32_t qf[4][4];
    float oacc[8][4] = {};
    float m_prev[2] = {-1e30f, -1e30f};
    float l_run[2] = {0.0f, 0.0f};
    const float scale = 0.125f;
    bool qload = false;

    for (int kt = 0; kt < nkt; kt++) {
        if (kt + 1 < nkt) { load_kv(kt + 1, (kt + 1) & 1); cpcommit(); cpwait1(); }
        else cpwait0();
        __syncthreads();

        if (!qload) {
            qload = true;
            #pragma unroll
            for (int ks = 0; ks < 4; ks++) {
                int row = wm * 16 + (lane & 15);
                int c = ks * 2 + (lane >> 4);
                ldsm4(qf[ks], swz(sQ, row, c));
            }
        }

        const uint32_t ss = sStage + (kt & 1) * ASTAGE;
        const bool doCompute = (kt * KTILE) <= (t0 + wm * 16 + 15);
        if (doCompute) {
            // ---- S = Q K^T (1 pass) ----
            float sacc[8][4] = {};
            #pragma unroll
            for (int ks = 0; ks < 4; ks++) {
                uint32_t bh[4][4];
                #pragma unroll
                for (int jj = 0; jj < 4; jj++) {
                    int row = jj * 16 + (lane & 7) + ((lane >> 4) << 3);
                    int c = ks * 2 + ((lane >> 3) & 1);
                    ldsm4(bh[jj], swz(ss, row, c));
                }
                #pragma unroll
                for (int nt = 0; nt < 8; nt++)
                    mma16816(sacc[nt], qf[ks], &bh[nt >> 1][(nt & 1) * 2]);
            }

            // ---- scale + causal mask ----
            const bool anyMask = (kt * KTILE + KTILE - 1) > (t0 + wm * 16);
            #pragma unroll
            for (int nt = 0; nt < 8; nt++)
                #pragma unroll
                for (int e = 0; e < 4; e++) {
                    float v = sacc[nt][e] * scale;
                    if (anyMask) {
                        int rg = t0 + wm * 16 + (lane >> 2) + (e >> 1) * 8;
                        int cg = kt * KTILE + nt * 8 + (lane & 3) * 2 + (e & 1);
                        if (cg > rg) v = -1e30f;
                    }
                    sacc[nt][e] = v;
                }

            // ---- online softmax ----
            #pragma unroll
            for (int rh = 0; rh < 2; rh++) {
                float mloc = -1e30f;
                #pragma unroll
                for (int nt = 0; nt < 8; nt++)
                    mloc = fmaxf(mloc, fmaxf(sacc[nt][rh * 2], sacc[nt][rh * 2 + 1]));
                mloc = fmaxf(mloc, __shfl_xor_sync(0xffffffffu, mloc, 1));
                mloc = fmaxf(mloc, __shfl_xor_sync(0xffffffffu, mloc, 2));
                float mnew = fmaxf(m_prev[rh], mloc);
                float corr = __expf(m_prev[rh] - mnew);
                m_prev[rh] = mnew;
                float ls = 0.0f;
                #pragma unroll
                for (int nt = 0; nt < 8; nt++) {
                    float p0 = __expf(sacc[nt][rh * 2]     - mnew);
                    float p1 = __expf(sacc[nt][rh * 2 + 1] - mnew);
                    sacc[nt][rh * 2] = p0; sacc[nt][rh * 2 + 1] = p1;
                    ls += p0 + p1;
                }
                ls += __shfl_xor_sync(0xffffffffu, ls, 1);
                ls += __shfl_xor_sync(0xffffffffu, ls, 2);
                l_run[rh] = l_run[rh] * corr + ls;
                #pragma unroll
                for (int nt = 0; nt < 8; nt++) {
                    oacc[nt][rh * 2]     *= corr;
                    oacc[nt][rh * 2 + 1] *= corr;
                }
            }

            // ---- O += P V (1 pass) ----
            #pragma unroll
            for (int jp = 0; jp < 4; jp++) {
                uint32_t pa[4];
                {
                    const float* f0 = sacc[2 * jp];
                    const float* f1 = sacc[2 * jp + 1];
                    pa[0] = f16x2_of(f0[0], f0[1]);
                    pa[1] = f16x2_of(f0[2], f0[3]);
                    pa[2] = f16x2_of(f1[0], f1[1]);
                    pa[3] = f16x2_of(f1[2], f1[3]);
                }
                uint32_t vh[4][4];
                #pragma unroll
                for (int jd = 0; jd < 4; jd++) {
                    int row = jp * 16 + (lane & 7) + (((lane >> 3) & 1) << 3);
                    int c = 2 * jd + (lane >> 4);
                    ldsm4t(vh[jd], swz(ss + 8192, row, c));
                }
                #pragma unroll
                for (int nt = 0; nt < 8; nt++)
                    mma16816(oacc[nt], pa, &vh[nt >> 1][(nt & 1) * 2]);
            }
        }
        __syncthreads();
    }

    // ---- epilogue: normalize, fp16, store ----
    float inv0 = 1.0f / l_run[0];
    float inv1 = 1.0f / l_run[1];
    #pragma unroll
    for (int nt = 0; nt < 8; nt++)
        #pragma unroll
        for (int rh = 0; rh < 2; rh++) {
            float iv = rh ? inv1 : inv0;
            float o0 = oacc[nt][rh * 2] * iv;
            float o1 = oacc[nt][rh * 2 + 1] * iv;
            size_t token = (size_t)(bT + t0 + wm * 16 + (lane >> 2) + rh * 8);
            of[(token * CC + h * HD + nt * 8 + (lane & 3) * 2) >> 1] = f16x2_of(o0, o1);
        }
}

// ---------------------------------------------------------------------------
// Launch
// ---------------------------------------------------------------------------
extern "C" void kernel_launch(void* const* d_in, const int* in_sizes, int n_in,
                              void* d_out, int out_size)
{
    const float* x      = (const float*)d_in[0];
    const float* qkv_w  = (const float*)d_in[1];
    const float* qkv_b  = (const float*)d_in[2];
    const float* out_w  = (const float*)d_in[3];
    const float* out_b  = (const float*)d_in[4];
    float* out = (float*)d_out;

    uint32_t *xf, *w1f, *w2f, *qf, *atf;
    cudaGetSymbolAddress((void**)&xf, g_xf);
    cudaGetSymbolAddress((void**)&w1f, g_w1f);
    cudaGetSymbolAddress((void**)&w2f, g_w2f);
    cudaGetSymbolAddress((void**)&qf, g_qkvf);
    cudaGetSymbolAddress((void**)&atf, g_atf);

    cudaFuncSetAttribute(gemm_mma<true>,  cudaFuncAttributeMaxDynamicSharedMemorySize, GEMM_DSM);
    cudaFuncSetAttribute(gemm_mma<false>, cudaFuncAttributeMaxDynamicSharedMemorySize, GEMM_DSM);
    cudaFuncSetAttribute(attn_mma, cudaFuncAttributeMaxDynamicSharedMemorySize, ATTN_DSM);

    // 0) convert x and weights to fp16
    {
        int n4 = MTOK * CC / 4;
        cvt_f16<<<n4 / 256, 256>>>((const float4*)x, xf, n4);
        n4 = C3 * CC / 4;
        cvt_f16<<<n4 / 256, 256>>>((const float4*)qkv_w, w1f, n4);
        n4 = CC * CC / 4;
        cvt_f16<<<n4 / 256, 256>>>((const float4*)out_w, w2f, n4);
    }
    // 1) QKV projection -> fp16 qkv
    {
        dim3 grid(C3 / 64, MTOK / 128);
        gemm_mma<true><<<grid, 256, GEMM_DSM>>>(xf, w1f, qkv_b, nullptr, qf, MTOK, C3, CC);
    }
    // 2) Causal flash attention -> fp16
    {
        dim3 grid(TT / QTILE, HH, BB);
        attn_mma<<<grid, 256, ATTN_DSM>>>(qf, atf);
    }
    // 3) Output projection -> fp32
    {
        dim3 grid(CC / 64, MTOK / 128);
        gemm_mma<false><<<grid, 256, GEMM_DSM>>>(atf, w2f, out_b, out, nullptr, MTOK, CC, CC);
    }
}

// round 9
// speedup vs baseline: 7.2788x; 1.0317x over previous
#include <cuda_runtime.h>
#include <cuda_fp16.h>
#include <cstdint>

// Problem constants
#define BB 4
#define TT 2048
#define CC 1024
#define HH 16
#define HD 64
#define MTOK (BB*TT)        // 8192
#define C3  (3*CC)          // 3072

// Scratch (allocation-guard-safe: __device__ globals). fp16 pairs stored as u32.
__device__ uint32_t g_xf[(size_t)MTOK * CC / 2];
__device__ uint32_t g_w1f[(size_t)C3 * CC / 2];
__device__ uint32_t g_w2f[(size_t)CC * CC / 2];
__device__ uint32_t g_qkvf[(size_t)MTOK * C3 / 2];
__device__ uint32_t g_atf[(size_t)MTOK * CC / 2];

// ---------------------------------------------------------------------------
// Helpers
// ---------------------------------------------------------------------------
__device__ __forceinline__ uint32_t smem_u32(const void* p) {
    uint32_t a;
    asm("{ .reg .u64 t; cvta.to.shared.u64 t, %1; cvt.u32.u64 %0, t; }" : "=r"(a) : "l"(p));
    return a;
}
// pack (lo,hi) -> f16x2 with 'lo' in LOW half
__device__ __forceinline__ uint32_t f16x2_of(float lo, float hi) {
    uint32_t r;
    asm("cvt.rn.f16x2.f32 %0, %1, %2;" : "=r"(r) : "f"(hi), "f"(lo));
    return r;
}
__device__ __forceinline__ void cp16(uint32_t s, const void* g) {
    asm volatile("cp.async.cg.shared.global [%0], [%1], 16;" :: "r"(s), "l"(g) : "memory");
}
__device__ __forceinline__ void cpcommit() {
    asm volatile("cp.async.commit_group;" ::: "memory");
}
__device__ __forceinline__ void cpwait0() { asm volatile("cp.async.wait_group 0;" ::: "memory"); }
__device__ __forceinline__ void cpwait1() { asm volatile("cp.async.wait_group 1;" ::: "memory"); }
__device__ __forceinline__ void ldsm4(uint32_t* r, uint32_t a) {
    asm volatile("ldmatrix.sync.aligned.m8n8.x4.shared.b16 {%0,%1,%2,%3}, [%4];"
        : "=r"(r[0]), "=r"(r[1]), "=r"(r[2]), "=r"(r[3]) : "r"(a));
}
__device__ __forceinline__ void ldsm4t(uint32_t* r, uint32_t a) {
    asm volatile("ldmatrix.sync.aligned.m8n8.x4.trans.shared.b16 {%0,%1,%2,%3}, [%4];"
        : "=r"(r[0]), "=r"(r[1]), "=r"(r[2]), "=r"(r[3]) : "r"(a));
}
__device__ __forceinline__ void mma16816(float* c, const uint32_t* a, const uint32_t* b) {
    asm volatile("mma.sync.aligned.m16n8k16.row.col.f32.f16.f16.f32 "
        "{%0,%1,%2,%3}, {%4,%5,%6,%7}, {%8,%9}, {%0,%1,%2,%3};"
        : "+f"(c[0]), "+f"(c[1]), "+f"(c[2]), "+f"(c[3])
        : "r"(a[0]), "r"(a[1]), "r"(a[2]), "r"(a[3]), "r"(b[0]), "r"(b[1]));
}

// 128B-row swizzle: 8 chunks of 16B, chunk ^ (row & 7)
__device__ __forceinline__ uint32_t swz(uint32_t base, int row, int chunk) {
    return base + (uint32_t)(row * 128) + (uint32_t)((chunk ^ (row & 7)) << 4);
}

// ---------------------------------------------------------------------------
// Conversion: fp32 -> fp16
// ---------------------------------------------------------------------------
__global__ void cvt_f16(const float4* __restrict__ in, uint32_t* __restrict__ o, int n4)
{
    int i = blockIdx.x * blockDim.x + threadIdx.x;
    if (i >= n4) return;
    float4 f = in[i];
    *(uint2*)&o[2 * i] = make_uint2(f16x2_of(f.x, f.y), f16x2_of(f.z, f.w));
}

// ---------------------------------------------------------------------------
// GEMM via mma.sync (single-pass fp16), BK=64, warp tile 64x32:
//   Out[m][n] = sum_k A[m][k]*W[n][k] + bias[n]
// CTA tile 128x128x64, 8 warps (2M x 4N), 3-stage cp.async.
// Stage = A 16K | B 16K = 32 KB. 128B rows, swizzle chunk ^ (row&7).
// smem bytes/MMA = 192 (vs 256 at 32x32) -> crossbar no longer binding.
// OUT_HALF=true writes fp16 (u32 pairs); else fp32.
// ---------------------------------------------------------------------------
#define BK 64
#define STAGES 3
#define SBYTES 32768
#define GEMM_DSM (STAGES * SBYTES + 1024)

template<bool OUT_HALF>
__global__ void __launch_bounds__(256, 2)
gemm_mma(const uint32_t* __restrict__ A2, const uint32_t* __restrict__ B2,
         const float* __restrict__ bias,
         float* __restrict__ OutF, uint32_t* __restrict__ OutH,
         int M, int N, int K)
{
    extern __shared__ char dsm[];
    const uint32_t sbase = (smem_u32(dsm) + 1023u) & ~1023u;

    const int tid  = threadIdx.x;
    const int lane = tid & 31;
    const int warp = tid >> 5;
    const int wm = warp & 1;        // 2 warps along M (64 rows each)
    const int wn = warp >> 1;       // 4 warps along N (32 cols each)
    const int m0 = blockIdx.y * 128;
    const int n0 = blockIdx.x * 128;

    // loaders: 128 rows x 8 chunks per tile; idx = i*256 + tid -> r = lr+i*32, c = lc
    const int lr = tid >> 3;        // 0..31
    const int lc = tid & 7;

    const char* pA = (const char*)A2 + (size_t)m0 * K * 2;
    const char* pB = (const char*)B2 + (size_t)n0 * K * 2;

    float acc[4][4][4] = {};
    const int NKI = K / BK;

    auto load_stage = [&](int s, int it) {
        const uint32_t ss = sbase + s * SBYTES;
        const int gko = it * BK * 2;
        #pragma unroll
        for (int i = 0; i < 4; i++) {
            int r = lr + i * 32;
            cp16(swz(ss, r, lc), pA + (size_t)r * K * 2 + gko + lc * 16);
            cp16(swz(ss + 16384, r, lc), pB + (size_t)r * K * 2 + gko + lc * 16);
        }
    };

    auto compute_stage = [&](int s) {
        const uint32_t ss = sbase + s * SBYTES;
        #pragma unroll
        for (int ks = 0; ks < 4; ks++) {
            uint32_t a[4][4];
            #pragma unroll
            for (int mt = 0; mt < 4; mt++) {
                int row = wm * 64 + mt * 16 + (lane & 15);
                int kc  = ks * 2 + (lane >> 4);
                ldsm4(a[mt], swz(ss, row, kc));
            }
            uint32_t b[2][4];
            #pragma unroll
            for (int jj = 0; jj < 2; jj++) {
                int row = wn * 32 + jj * 16 + (lane & 7) + ((lane >> 4) << 3);
                int kc  = ks * 2 + ((lane >> 3) & 1);
                ldsm4(b[jj], swz(ss + 16384, row, kc));
            }
            #pragma unroll
            for (int mt = 0; mt < 4; mt++)
                #pragma unroll
                for (int nt = 0; nt < 4; nt++)
                    mma16816(acc[mt][nt], a[mt], &b[nt >> 1][(nt & 1) * 2]);
        }
    };

    #pragma unroll
    for (int s = 0; s < STAGES - 1; s++) { load_stage(s, s); cpcommit(); }

    for (int it = 0; it < NKI; it++) {
        asm volatile("cp.async.wait_group %0;" :: "n"(STAGES - 2) : "memory");
        __syncthreads();
        const int nit = it + STAGES - 1;
        if (nit < NKI) load_stage(nit % STAGES, nit);
        cpcommit();
        compute_stage(it % STAGES);
    }

    const int rr = lane >> 2;
    const int cc = (lane & 3) * 2;
    #pragma unroll
    for (int mt = 0; mt < 4; mt++)
        #pragma unroll
        for (int nt = 0; nt < 4; nt++) {
            const int col = n0 + wn * 32 + nt * 8 + cc;
            const float b0 = bias[col], b1 = bias[col + 1];
            #pragma unroll
            for (int hf = 0; hf < 2; hf++) {
                const int row = m0 + wm * 64 + mt * 16 + rr + hf * 8;
                float v0 = acc[mt][nt][hf * 2 + 0] + b0;
                float v1 = acc[mt][nt][hf * 2 + 1] + b1;
                if (OUT_HALF) {
                    OutH[((size_t)row * N + col) >> 1] = f16x2_of(v0, v1);
                } else {
                    *(float2*)&OutF[(size_t)row * N + col] = make_float2(v0, v1);
                }
            }
        }
}

// ---------------------------------------------------------------------------
// Flash attention (causal), single-pass fp16 mma.sync (unchanged from R8).
// ---------------------------------------------------------------------------
#define QTILE 128
#define KTILE 64
#define ASTAGE 16384
#define ATTN_DSM (16384 + 2 * ASTAGE + 1024)

__global__ void __launch_bounds__(256, 1)
attn_mma(const uint32_t* __restrict__ qkvf, uint32_t* __restrict__ of)
{
    extern __shared__ char dsm[];
    const uint32_t sb = (smem_u32(dsm) + 1023u) & ~1023u;
    const uint32_t sQ = sb, sStage = sb + 16384;

    const int tid = threadIdx.x;
    const int lane = tid & 31;
    const int wm = tid >> 5;
    const int qt = blockIdx.x;
    const int h  = blockIdx.y;
    const int b  = blockIdx.z;
    const int t0 = qt * QTILE;
    const int bT = b * TT;

    const char* pf = (const char*)qkvf;
    const int nkt = 2 * (qt + 1);

    auto load_q = [&]() {
        #pragma unroll
        for (int i = 0; i < 4; i++) {
            int idx = i * 256 + tid;
            int r = idx >> 3, c = idx & 7;
            cp16(swz(sQ, r, c), pf + ((size_t)(bT + t0 + r) * C3 + h * HD) * 2 + c * 16);
        }
    };
    auto load_kv = [&](int kt, int buf) {
        const uint32_t ss = sStage + buf * ASTAGE;
        int r = tid >> 2;
        int cbase = (tid & 3) * 2;
        size_t rowg = (size_t)(bT + kt * KTILE + r) * C3;
        size_t kb = (rowg + CC + h * HD) * 2;
        size_t vb = (rowg + 2 * CC + h * HD) * 2;
        #pragma unroll
        for (int j = 0; j < 2; j++) {
            int c = cbase + j;
            cp16(swz(ss,        r, c), pf + kb + c * 16);
            cp16(swz(ss + 8192, r, c), pf + vb + c * 16);
        }
    };

    load_q();
    load_kv(0, 0);
    cpcommit();

    uint32_t qf[4][4];
    float oacc[8][4] = {};
    float m_prev[2] = {-1e30f, -1e30f};
    float l_run[2] = {0.0f, 0.0f};
    const float scale = 0.125f;
    bool qload = false;

    for (int kt = 0; kt < nkt; kt++) {
        if (kt + 1 < nkt) { load_kv(kt + 1, (kt + 1) & 1); cpcommit(); cpwait1(); }
        else cpwait0();
        __syncthreads();

        if (!qload) {
            qload = true;
            #pragma unroll
            for (int ks = 0; ks < 4; ks++) {
                int row = wm * 16 + (lane & 15);
                int c = ks * 2 + (lane >> 4);
                ldsm4(qf[ks], swz(sQ, row, c));
            }
        }

        const uint32_t ss = sStage + (kt & 1) * ASTAGE;
        const bool doCompute = (kt * KTILE) <= (t0 + wm * 16 + 15);
        if (doCompute) {
            // ---- S = Q K^T (1 pass) ----
            float sacc[8][4] = {};
            #pragma unroll
            for (int ks = 0; ks < 4; ks++) {
                uint32_t bh[4][4];
                #pragma unroll
                for (int jj = 0; jj < 4; jj++) {
                    int row = jj * 16 + (lane & 7) + ((lane >> 4) << 3);
                    int c = ks * 2 + ((lane >> 3) & 1);
                    ldsm4(bh[jj], swz(ss, row, c));
                }
                #pragma unroll
                for (int nt = 0; nt < 8; nt++)
                    mma16816(sacc[nt], qf[ks], &bh[nt >> 1][(nt & 1) * 2]);
            }

            // ---- scale + causal mask ----
            const bool anyMask = (kt * KTILE + KTILE - 1) > (t0 + wm * 16);
            #pragma unroll
            for (int nt = 0; nt < 8; nt++)
                #pragma unroll
                for (int e = 0; e < 4; e++) {
                    float v = sacc[nt][e] * scale;
                    if (anyMask) {
                        int rg = t0 + wm * 16 + (lane >> 2) + (e >> 1) * 8;
                        int cg = kt * KTILE + nt * 8 + (lane & 3) * 2 + (e & 1);
                        if (cg > rg) v = -1e30f;
                    }
                    sacc[nt][e] = v;
                }

            // ---- online softmax ----
            #pragma unroll
            for (int rh = 0; rh < 2; rh++) {
                float mloc = -1e30f;
                #pragma unroll
                for (int nt = 0; nt < 8; nt++)
                    mloc = fmaxf(mloc, fmaxf(sacc[nt][rh * 2], sacc[nt][rh * 2 + 1]));
                mloc = fmaxf(mloc, __shfl_xor_sync(0xffffffffu, mloc, 1));
                mloc = fmaxf(mloc, __shfl_xor_sync(0xffffffffu, mloc, 2));
                float mnew = fmaxf(m_prev[rh], mloc);
                float corr = __expf(m_prev[rh] - mnew);
                m_prev[rh] = mnew;
                float ls = 0.0f;
                #pragma unroll
                for (int nt = 0; nt < 8; nt++) {
                    float p0 = __expf(sacc[nt][rh * 2]     - mnew);
                    float p1 = __expf(sacc[nt][rh * 2 + 1] - mnew);
                    sacc[nt][rh * 2] = p0; sacc[nt][rh * 2 + 1] = p1;
                    ls += p0 + p1;
                }
                ls += __shfl_xor_sync(0xffffffffu, ls, 1);
                ls += __shfl_xor_sync(0xffffffffu, ls, 2);
                l_run[rh] = l_run[rh] * corr + ls;
                #pragma unroll
                for (int nt = 0; nt < 8; nt++) {
                    oacc[nt][rh * 2]     *= corr;
                    oacc[nt][rh * 2 + 1] *= corr;
                }
            }

            // ---- O += P V (1 pass) ----
            #pragma unroll
            for (int jp = 0; jp < 4; jp++) {
                uint32_t pa[4];
                {
                    const float* f0 = sacc[2 * jp];
                    const float* f1 = sacc[2 * jp + 1];
                    pa[0] = f16x2_of(f0[0], f0[1]);
                    pa[1] = f16x2_of(f0[2], f0[3]);
                    pa[2] = f16x2_of(f1[0], f1[1]);
                    pa[3] = f16x2_of(f1[2], f1[3]);
                }
                uint32_t vh[4][4];
                #pragma unroll
                for (int jd = 0; jd < 4; jd++) {
                    int row = jp * 16 + (lane & 7) + (((lane >> 3) & 1) << 3);
                    int c = 2 * jd + (lane >> 4);
                    ldsm4t(vh[jd], swz(ss + 8192, row, c));
                }
                #pragma unroll
                for (int nt = 0; nt < 8; nt++)
                    mma16816(oacc[nt], pa, &vh[nt >> 1][(nt & 1) * 2]);
            }
        }
        __syncthreads();
    }

    // ---- epilogue: normalize, fp16, store ----
    float inv0 = 1.0f / l_run[0];
    float inv1 = 1.0f / l_run[1];
    #pragma unroll
    for (int nt = 0; nt < 8; nt++)
        #pragma unroll
        for (int rh = 0; rh < 2; rh++) {
            float iv = rh ? inv1 : inv0;
            float o0 = oacc[nt][rh * 2] * iv;
            float o1 = oacc[nt][rh * 2 + 1] * iv;
            size_t token = (size_t)(bT + t0 + wm * 16 + (lane >> 2) + rh * 8);
            of[(token * CC + h * HD + nt * 8 + (lane & 3) * 2) >> 1] = f16x2_of(o0, o1);
        }
}

// ---------------------------------------------------------------------------
// Launch
// ---------------------------------------------------------------------------
extern "C" void kernel_launch(void* const* d_in, const int* in_sizes, int n_in,
                              void* d_out, int out_size)
{
    const float* x      = (const float*)d_in[0];
    const float* qkv_w  = (const float*)d_in[1];
    const float* qkv_b  = (const float*)d_in[2];
    const float* out_w  = (const float*)d_in[3];
    const float* out_b  = (const float*)d_in[4];
    float* out = (float*)d_out;

    uint32_t *xf, *w1f, *w2f, *qf, *atf;
    cudaGetSymbolAddress((void**)&xf, g_xf);
    cudaGetSymbolAddress((void**)&w1f, g_w1f);
    cudaGetSymbolAddress((void**)&w2f, g_w2f);
    cudaGetSymbolAddress((void**)&qf, g_qkvf);
    cudaGetSymbolAddress((void**)&atf, g_atf);

    cudaFuncSetAttribute(gemm_mma<true>,  cudaFuncAttributeMaxDynamicSharedMemorySize, GEMM_DSM);
    cudaFuncSetAttribute(gemm_mma<false>, cudaFuncAttributeMaxDynamicSharedMemorySize, GEMM_DSM);
    cudaFuncSetAttribute(attn_mma, cudaFuncAttributeMaxDynamicSharedMemorySize, ATTN_DSM);

    // 0) convert x and weights to fp16
    {
        int n4 = MTOK * CC / 4;
        cvt_f16<<<n4 / 256, 256>>>((const float4*)x, xf, n4);
        n4 = C3 * CC / 4;
        cvt_f16<<<n4 / 256, 256>>>((const float4*)qkv_w, w1f, n4);
        n4 = CC * CC / 4;
        cvt_f16<<<n4 / 256, 256>>>((const float4*)out_w, w2f, n4);
    }
    // 1) QKV projection -> fp16 qkv
    {
        dim3 grid(C3 / 128, MTOK / 128);
        gemm_mma<true><<<grid, 256, GEMM_DSM>>>(xf, w1f, qkv_b, nullptr, qf, MTOK, C3, CC);
    }
    // 2) Causal flash attention -> fp16
    {
        dim3 grid(TT / QTILE, HH, BB);
        attn_mma<<<grid, 256, ATTN_DSM>>>(qf, atf);
    }
    // 3) Output projection -> fp32
    {
        dim3 grid(CC / 128, MTOK / 128);
        gemm_mma<false><<<grid, 256, GEMM_DSM>>>(atf, w2f, out_b, out, nullptr, MTOK, CC, CC);
    }
}

// round 10
// speedup vs baseline: 7.5973x; 1.0437x over previous
#include <cuda_runtime.h>
#include <cuda_fp16.h>
#include <cstdint>

// Problem constants
#define BB 4
#define TT 2048
#define CC 1024
#define HH 16
#define HD 64
#define MTOK (BB*TT)        // 8192
#define C3  (3*CC)          // 3072

// Scratch (allocation-guard-safe: __device__ globals). fp16 pairs stored as u32.
__device__ uint32_t g_xf[(size_t)MTOK * CC / 2];
__device__ uint32_t g_w1f[(size_t)C3 * CC / 2];
__device__ uint32_t g_w2f[(size_t)CC * CC / 2];
__device__ uint32_t g_qkvf[(size_t)MTOK * C3 / 2];
__device__ uint32_t g_atf[(size_t)MTOK * CC / 2];

// ---------------------------------------------------------------------------
// Helpers
// ---------------------------------------------------------------------------
__device__ __forceinline__ uint32_t smem_u32(const void* p) {
    uint32_t a;
    asm("{ .reg .u64 t; cvta.to.shared.u64 t, %1; cvt.u32.u64 %0, t; }" : "=r"(a) : "l"(p));
    return a;
}
// pack (lo,hi) -> f16x2 with 'lo' in LOW half
__device__ __forceinline__ uint32_t f16x2_of(float lo, float hi) {
    uint32_t r;
    asm("cvt.rn.f16x2.f32 %0, %1, %2;" : "=r"(r) : "f"(hi), "f"(lo));
    return r;
}
__device__ __forceinline__ void cp16(uint32_t s, const void* g) {
    asm volatile("cp.async.cg.shared.global [%0], [%1], 16;" :: "r"(s), "l"(g) : "memory");
}
__device__ __forceinline__ void cpcommit() {
    asm volatile("cp.async.commit_group;" ::: "memory");
}
__device__ __forceinline__ void cpwait0() { asm volatile("cp.async.wait_group 0;" ::: "memory"); }
__device__ __forceinline__ void cpwait1() { asm volatile("cp.async.wait_group 1;" ::: "memory"); }
__device__ __forceinline__ void ldsm4(uint32_t* r, uint32_t a) {
    asm volatile("ldmatrix.sync.aligned.m8n8.x4.shared.b16 {%0,%1,%2,%3}, [%4];"
        : "=r"(r[0]), "=r"(r[1]), "=r"(r[2]), "=r"(r[3]) : "r"(a));
}
__device__ __forceinline__ void ldsm4t(uint32_t* r, uint32_t a) {
    asm volatile("ldmatrix.sync.aligned.m8n8.x4.trans.shared.b16 {%0,%1,%2,%3}, [%4];"
        : "=r"(r[0]), "=r"(r[1]), "=r"(r[2]), "=r"(r[3]) : "r"(a));
}
__device__ __forceinline__ void mma16816(float* c, const uint32_t* a, const uint32_t* b) {
    asm volatile("mma.sync.aligned.m16n8k16.row.col.f32.f16.f16.f32 "
        "{%0,%1,%2,%3}, {%4,%5,%6,%7}, {%8,%9}, {%0,%1,%2,%3};"
        : "+f"(c[0]), "+f"(c[1]), "+f"(c[2]), "+f"(c[3])
        : "r"(a[0]), "r"(a[1]), "r"(a[2]), "r"(a[3]), "r"(b[0]), "r"(b[1]));
}

// 128B-row swizzle: 8 chunks of 16B, chunk ^ (row & 7)
__device__ __forceinline__ uint32_t swz(uint32_t base, int row, int chunk) {
    return base + (uint32_t)(row * 128) + (uint32_t)((chunk ^ (row & 7)) << 4);
}

// ---------------------------------------------------------------------------
// Conversion: fp32 -> fp16
// ---------------------------------------------------------------------------
__global__ void cvt_f16(const float4* __restrict__ in, uint32_t* __restrict__ o, int n4)
{
    int i = blockIdx.x * blockDim.x + threadIdx.x;
    if (i >= n4) return;
    float4 f = in[i];
    *(uint2*)&o[2 * i] = make_uint2(f16x2_of(f.x, f.y), f16x2_of(f.z, f.w));
}

// ---------------------------------------------------------------------------
// GEMM via mma.sync (single-pass fp16), BK=64, warp tile 64x32 (from R9).
// ---------------------------------------------------------------------------
#define BK 64
#define STAGES 3
#define SBYTES 32768
#define GEMM_DSM (STAGES * SBYTES + 1024)

template<bool OUT_HALF>
__global__ void __launch_bounds__(256, 2)
gemm_mma(const uint32_t* __restrict__ A2, const uint32_t* __restrict__ B2,
         const float* __restrict__ bias,
         float* __restrict__ OutF, uint32_t* __restrict__ OutH,
         int M, int N, int K)
{
    extern __shared__ char dsm[];
    const uint32_t sbase = (smem_u32(dsm) + 1023u) & ~1023u;

    const int tid  = threadIdx.x;
    const int lane = tid & 31;
    const int warp = tid >> 5;
    const int wm = warp & 1;
    const int wn = warp >> 1;
    const int m0 = blockIdx.y * 128;
    const int n0 = blockIdx.x * 128;

    const int lr = tid >> 3;
    const int lc = tid & 7;

    const char* pA = (const char*)A2 + (size_t)m0 * K * 2;
    const char* pB = (const char*)B2 + (size_t)n0 * K * 2;

    float acc[4][4][4] = {};
    const int NKI = K / BK;

    auto load_stage = [&](int s, int it) {
        const uint32_t ss = sbase + s * SBYTES;
        const int gko = it * BK * 2;
        #pragma unroll
        for (int i = 0; i < 4; i++) {
            int r = lr + i * 32;
            cp16(swz(ss, r, lc), pA + (size_t)r * K * 2 + gko + lc * 16);
            cp16(swz(ss + 16384, r, lc), pB + (size_t)r * K * 2 + gko + lc * 16);
        }
    };

    auto compute_stage = [&](int s) {
        const uint32_t ss = sbase + s * SBYTES;
        #pragma unroll
        for (int ks = 0; ks < 4; ks++) {
            uint32_t a[4][4];
            #pragma unroll
            for (int mt = 0; mt < 4; mt++) {
                int row = wm * 64 + mt * 16 + (lane & 15);
                int kc  = ks * 2 + (lane >> 4);
                ldsm4(a[mt], swz(ss, row, kc));
            }
            uint32_t b[2][4];
            #pragma unroll
            for (int jj = 0; jj < 2; jj++) {
                int row = wn * 32 + jj * 16 + (lane & 7) + ((lane >> 4) << 3);
                int kc  = ks * 2 + ((lane >> 3) & 1);
                ldsm4(b[jj], swz(ss + 16384, row, kc));
            }
            #pragma unroll
            for (int mt = 0; mt < 4; mt++)
                #pragma unroll
                for (int nt = 0; nt < 4; nt++)
                    mma16816(acc[mt][nt], a[mt], &b[nt >> 1][(nt & 1) * 2]);
        }
    };

    #pragma unroll
    for (int s = 0; s < STAGES - 1; s++) { load_stage(s, s); cpcommit(); }

    for (int it = 0; it < NKI; it++) {
        asm volatile("cp.async.wait_group %0;" :: "n"(STAGES - 2) : "memory");
        __syncthreads();
        const int nit = it + STAGES - 1;
        if (nit < NKI) load_stage(nit % STAGES, nit);
        cpcommit();
        compute_stage(it % STAGES);
    }

    const int rr = lane >> 2;
    const int cc = (lane & 3) * 2;
    #pragma unroll
    for (int mt = 0; mt < 4; mt++)
        #pragma unroll
        for (int nt = 0; nt < 4; nt++) {
            const int col = n0 + wn * 32 + nt * 8 + cc;
            const float b0 = bias[col], b1 = bias[col + 1];
            #pragma unroll
            for (int hf = 0; hf < 2; hf++) {
                const int row = m0 + wm * 64 + mt * 16 + rr + hf * 8;
                float v0 = acc[mt][nt][hf * 2 + 0] + b0;
                float v1 = acc[mt][nt][hf * 2 + 1] + b1;
                if (OUT_HALF) {
                    OutH[((size_t)row * N + col) >> 1] = f16x2_of(v0, v1);
                } else {
                    *(float2*)&OutF[(size_t)row * N + col] = make_float2(v0, v1);
                }
            }
        }
}

// ---------------------------------------------------------------------------
// Flash attention (causal), single-pass fp16, warp M-tile 32 (QTILE=256):
// Grid (T/256, H, B), 256 threads; warp w owns q rows w*32..w*32+31.
// smem: Q 32K + 2 stages x (K 8K | V 8K). bytes/MMA ~160 (was 256).
// qt reversed so heavy causal tiles are scheduled first.
// ---------------------------------------------------------------------------
#define QTILE 256
#define KTILE 64
#define ASTAGE 16384
#define ATTN_DSM (32768 + 2 * ASTAGE + 1024)

__global__ void __launch_bounds__(256, 1)
attn_mma(const uint32_t* __restrict__ qkvf, uint32_t* __restrict__ of)
{
    extern __shared__ char dsm[];
    const uint32_t sb = (smem_u32(dsm) + 1023u) & ~1023u;
    const uint32_t sQ = sb, sStage = sb + 32768;

    const int tid = threadIdx.x;
    const int lane = tid & 31;
    const int wm = tid >> 5;
    const int qt = (int)gridDim.x - 1 - (int)blockIdx.x;   // heavy tiles first
    const int h  = blockIdx.y;
    const int b  = blockIdx.z;
    const int t0 = qt * QTILE;
    const int bT = b * TT;

    const char* pf = (const char*)qkvf;
    const int nkt = 4 * (qt + 1);

    auto load_q = [&]() {
        #pragma unroll
        for (int i = 0; i < 8; i++) {
            int idx = i * 256 + tid;
            int r = idx >> 3, c = idx & 7;
            cp16(swz(sQ, r, c), pf + ((size_t)(bT + t0 + r) * C3 + h * HD) * 2 + c * 16);
        }
    };
    auto load_kv = [&](int kt, int buf) {
        const uint32_t ss = sStage + buf * ASTAGE;
        int r = tid >> 2;
        int cbase = (tid & 3) * 2;
        size_t rowg = (size_t)(bT + kt * KTILE + r) * C3;
        size_t kb = (rowg + CC + h * HD) * 2;
        size_t vb = (rowg + 2 * CC + h * HD) * 2;
        #pragma unroll
        for (int j = 0; j < 2; j++) {
            int c = cbase + j;
            cp16(swz(ss,        r, c), pf + kb + c * 16);
            cp16(swz(ss + 8192, r, c), pf + vb + c * 16);
        }
    };

    load_q();
    load_kv(0, 0);
    cpcommit();

    uint32_t qf[2][4][4];
    float oacc[2][8][4] = {};
    float m_prev[2][2] = {{-1e30f, -1e30f}, {-1e30f, -1e30f}};
    float l_run[2][2] = {};
    const float scale = 0.125f;
    bool qload = false;

    for (int kt = 0; kt < nkt; kt++) {
        if (kt + 1 < nkt) { load_kv(kt + 1, (kt + 1) & 1); cpcommit(); cpwait1(); }
        else cpwait0();
        __syncthreads();

        if (!qload) {
            qload = true;
            #pragma unroll
            for (int mt = 0; mt < 2; mt++)
                #pragma unroll
                for (int ks = 0; ks < 4; ks++) {
                    int row = wm * 32 + mt * 16 + (lane & 15);
                    int c = ks * 2 + (lane >> 4);
                    ldsm4(qf[mt][ks], swz(sQ, row, c));
                }
        }

        const uint32_t ss = sStage + (kt & 1) * ASTAGE;
        const bool doCompute = (kt * KTILE) <= (t0 + wm * 32 + 31);
        if (doCompute) {
            // ---- S = Q K^T ----
            float sacc[2][8][4] = {};
            #pragma unroll
            for (int ks = 0; ks < 4; ks++) {
                uint32_t bh[4][4];
                #pragma unroll
                for (int jj = 0; jj < 4; jj++) {
                    int row = jj * 16 + (lane & 7) + ((lane >> 4) << 3);
                    int c = ks * 2 + ((lane >> 3) & 1);
                    ldsm4(bh[jj], swz(ss, row, c));
                }
                #pragma unroll
                for (int mt = 0; mt < 2; mt++)
                    #pragma unroll
                    for (int nt = 0; nt < 8; nt++)
                        mma16816(sacc[mt][nt], qf[mt][ks], &bh[nt >> 1][(nt & 1) * 2]);
            }

            // ---- scale + causal mask + online softmax (per mt) ----
            #pragma unroll
            for (int mt = 0; mt < 2; mt++) {
                const int rbase = t0 + wm * 32 + mt * 16;
                const bool anyMask = (kt * KTILE + KTILE - 1) > rbase;
                #pragma unroll
                for (int nt = 0; nt < 8; nt++)
                    #pragma unroll
                    for (int e = 0; e < 4; e++) {
                        float v = sacc[mt][nt][e] * scale;
                        if (anyMask) {
                            int rg = rbase + (lane >> 2) + (e >> 1) * 8;
                            int cg = kt * KTILE + nt * 8 + (lane & 3) * 2 + (e & 1);
                            if (cg > rg) v = -1e30f;
                        }
                        sacc[mt][nt][e] = v;
                    }

                #pragma unroll
                for (int rh = 0; rh < 2; rh++) {
                    float mloc = -1e30f;
                    #pragma unroll
                    for (int nt = 0; nt < 8; nt++)
                        mloc = fmaxf(mloc, fmaxf(sacc[mt][nt][rh * 2], sacc[mt][nt][rh * 2 + 1]));
                    mloc = fmaxf(mloc, __shfl_xor_sync(0xffffffffu, mloc, 1));
                    mloc = fmaxf(mloc, __shfl_xor_sync(0xffffffffu, mloc, 2));
                    float mnew = fmaxf(m_prev[mt][rh], mloc);
                    float corr = __expf(m_prev[mt][rh] - mnew);
                    m_prev[mt][rh] = mnew;
                    float ls = 0.0f;
                    #pragma unroll
                    for (int nt = 0; nt < 8; nt++) {
                        float p0 = __expf(sacc[mt][nt][rh * 2]     - mnew);
                        float p1 = __expf(sacc[mt][nt][rh * 2 + 1] - mnew);
                        sacc[mt][nt][rh * 2] = p0; sacc[mt][nt][rh * 2 + 1] = p1;
                        ls += p0 + p1;
                    }
                    ls += __shfl_xor_sync(0xffffffffu, ls, 1);
                    ls += __shfl_xor_sync(0xffffffffu, ls, 2);
                    l_run[mt][rh] = l_run[mt][rh] * corr + ls;
                    #pragma unroll
                    for (int nt = 0; nt < 8; nt++) {
                        oacc[mt][nt][rh * 2]     *= corr;
                        oacc[mt][nt][rh * 2 + 1] *= corr;
                    }
                }
            }

            // ---- O += P V ----
            #pragma unroll
            for (int jp = 0; jp < 4; jp++) {
                uint32_t vh[4][4];
                #pragma unroll
                for (int jd = 0; jd < 4; jd++) {
                    int row = jp * 16 + (lane & 7) + (((lane >> 3) & 1) << 3);
                    int c = 2 * jd + (lane >> 4);
                    ldsm4t(vh[jd], swz(ss + 8192, row, c));
                }
                #pragma unroll
                for (int mt = 0; mt < 2; mt++) {
                    uint32_t pa[4];
                    const float* f0 = sacc[mt][2 * jp];
                    const float* f1 = sacc[mt][2 * jp + 1];
                    pa[0] = f16x2_of(f0[0], f0[1]);
                    pa[1] = f16x2_of(f0[2], f0[3]);
                    pa[2] = f16x2_of(f1[0], f1[1]);
                    pa[3] = f16x2_of(f1[2], f1[3]);
                    #pragma unroll
                    for (int nt = 0; nt < 8; nt++)
                        mma16816(oacc[mt][nt], pa, &vh[nt >> 1][(nt & 1) * 2]);
                }
            }
        }
        __syncthreads();
    }

    // ---- epilogue: normalize, fp16, store ----
    #pragma unroll
    for (int mt = 0; mt < 2; mt++)
        #pragma unroll
        for (int rh = 0; rh < 2; rh++) {
            float iv = 1.0f / l_run[mt][rh];
            #pragma unroll
            for (int nt = 0; nt < 8; nt++) {
                float o0 = oacc[mt][nt][rh * 2] * iv;
                float o1 = oacc[mt][nt][rh * 2 + 1] * iv;
                size_t token = (size_t)(bT + t0 + wm * 32 + mt * 16 + (lane >> 2) + rh * 8);
                of[(token * CC + h * HD + nt * 8 + (lane & 3) * 2) >> 1] = f16x2_of(o0, o1);
            }
        }
}

// ---------------------------------------------------------------------------
// Launch
// ---------------------------------------------------------------------------
extern "C" void kernel_launch(void* const* d_in, const int* in_sizes, int n_in,
                              void* d_out, int out_size)
{
    const float* x      = (const float*)d_in[0];
    const float* qkv_w  = (const float*)d_in[1];
    const float* qkv_b  = (const float*)d_in[2];
    const float* out_w  = (const float*)d_in[3];
    const float* out_b  = (const float*)d_in[4];
    float* out = (float*)d_out;

    uint32_t *xf, *w1f, *w2f, *qf, *atf;
    cudaGetSymbolAddress((void**)&xf, g_xf);
    cudaGetSymbolAddress((void**)&w1f, g_w1f);
    cudaGetSymbolAddress((void**)&w2f, g_w2f);
    cudaGetSymbolAddress((void**)&qf, g_qkvf);
    cudaGetSymbolAddress((void**)&atf, g_atf);

    cudaFuncSetAttribute(gemm_mma<true>,  cudaFuncAttributeMaxDynamicSharedMemorySize, GEMM_DSM);
    cudaFuncSetAttribute(gemm_mma<false>, cudaFuncAttributeMaxDynamicSharedMemorySize, GEMM_DSM);
    cudaFuncSetAttribute(attn_mma, cudaFuncAttributeMaxDynamicSharedMemorySize, ATTN_DSM);

    // 0) convert x and weights to fp16
    {
        int n4 = MTOK * CC / 4;
        cvt_f16<<<n4 / 256, 256>>>((const float4*)x, xf, n4);
        n4 = C3 * CC / 4;
        cvt_f16<<<n4 / 256, 256>>>((const float4*)qkv_w, w1f, n4);
        n4 = CC * CC / 4;
        cvt_f16<<<n4 / 256, 256>>>((const float4*)out_w, w2f, n4);
    }
    // 1) QKV projection -> fp16 qkv
    {
        dim3 grid(C3 / 128, MTOK / 128);
        gemm_mma<true><<<grid, 256, GEMM_DSM>>>(xf, w1f, qkv_b, nullptr, qf, MTOK, C3, CC);
    }
    // 2) Causal flash attention -> fp16
    {
        dim3 grid(TT / QTILE, HH, BB);
        attn_mma<<<grid, 256, ATTN_DSM>>>(qf, atf);
    }
    // 3) Output projection -> fp32
    {
        dim3 grid(CC / 128, MTOK / 128);
        gemm_mma<false><<<grid, 256, GEMM_DSM>>>(atf, w2f, out_b, out, nullptr, MTOK, CC, CC);
    }
}

// round 11
// speedup vs baseline: 7.7318x; 1.0177x over previous
#include <cuda_runtime.h>
#include <cuda_fp16.h>
#include <cstdint>

// Problem constants
#define BB 4
#define TT 2048
#define CC 1024
#define HH 16
#define HD 64
#define MTOK (BB*TT)        // 8192
#define C3  (3*CC)          // 3072

// Scratch (allocation-guard-safe: __device__ globals). fp16 pairs stored as u32.
__device__ uint32_t g_xf[(size_t)MTOK * CC / 2];
__device__ uint32_t g_w1f[(size_t)C3 * CC / 2];
__device__ uint32_t g_w2f[(size_t)CC * CC / 2];
__device__ uint32_t g_qkvf[(size_t)MTOK * C3 / 2];
__device__ uint32_t g_atf[(size_t)MTOK * CC / 2];

// ---------------------------------------------------------------------------
// Helpers
// ---------------------------------------------------------------------------
__device__ __forceinline__ uint32_t smem_u32(const void* p) {
    uint32_t a;
    asm("{ .reg .u64 t; cvta.to.shared.u64 t, %1; cvt.u32.u64 %0, t; }" : "=r"(a) : "l"(p));
    return a;
}
// pack (lo,hi) -> f16x2 with 'lo' in LOW half
__device__ __forceinline__ uint32_t f16x2_of(float lo, float hi) {
    uint32_t r;
    asm("cvt.rn.f16x2.f32 %0, %1, %2;" : "=r"(r) : "f"(hi), "f"(lo));
    return r;
}
__device__ __forceinline__ void cp16(uint32_t s, const void* g) {
    asm volatile("cp.async.cg.shared.global [%0], [%1], 16;" :: "r"(s), "l"(g) : "memory");
}
__device__ __forceinline__ void cpcommit() {
    asm volatile("cp.async.commit_group;" ::: "memory");
}
__device__ __forceinline__ void cpwait0() { asm volatile("cp.async.wait_group 0;" ::: "memory"); }
__device__ __forceinline__ void cpwait1() { asm volatile("cp.async.wait_group 1;" ::: "memory"); }
__device__ __forceinline__ void ldsm4(uint32_t* r, uint32_t a) {
    asm volatile("ldmatrix.sync.aligned.m8n8.x4.shared.b16 {%0,%1,%2,%3}, [%4];"
        : "=r"(r[0]), "=r"(r[1]), "=r"(r[2]), "=r"(r[3]) : "r"(a));
}
__device__ __forceinline__ void ldsm4t(uint32_t* r, uint32_t a) {
    asm volatile("ldmatrix.sync.aligned.m8n8.x4.trans.shared.b16 {%0,%1,%2,%3}, [%4];"
        : "=r"(r[0]), "=r"(r[1]), "=r"(r[2]), "=r"(r[3]) : "r"(a));
}
__device__ __forceinline__ void mma16816(float* c, const uint32_t* a, const uint32_t* b) {
    asm volatile("mma.sync.aligned.m16n8k16.row.col.f32.f16.f16.f32 "
        "{%0,%1,%2,%3}, {%4,%5,%6,%7}, {%8,%9}, {%0,%1,%2,%3};"
        : "+f"(c[0]), "+f"(c[1]), "+f"(c[2]), "+f"(c[3])
        : "r"(a[0]), "r"(a[1]), "r"(a[2]), "r"(a[3]), "r"(b[0]), "r"(b[1]));
}

// 128B-row swizzle: 8 chunks of 16B, chunk ^ (row & 7)
__device__ __forceinline__ uint32_t swz(uint32_t base, int row, int chunk) {
    return base + (uint32_t)(row * 128) + (uint32_t)((chunk ^ (row & 7)) << 4);
}

// ---------------------------------------------------------------------------
// Conversion: fp32 -> fp16
// ---------------------------------------------------------------------------
__global__ void cvt_f16(const float4* __restrict__ in, uint32_t* __restrict__ o, int n4)
{
    int i = blockIdx.x * blockDim.x + threadIdx.x;
    if (i >= n4) return;
    float4 f = in[i];
    *(uint2*)&o[2 * i] = make_uint2(f16x2_of(f.x, f.y), f16x2_of(f.z, f.w));
}

// ---------------------------------------------------------------------------
// GEMM via mma.sync (single-pass fp16), BK=64, warp tile 64x32 (unchanged R9).
// ---------------------------------------------------------------------------
#define BK 64
#define STAGES 3
#define SBYTES 32768
#define GEMM_DSM (STAGES * SBYTES + 1024)

template<bool OUT_HALF>
__global__ void __launch_bounds__(256, 2)
gemm_mma(const uint32_t* __restrict__ A2, const uint32_t* __restrict__ B2,
         const float* __restrict__ bias,
         float* __restrict__ OutF, uint32_t* __restrict__ OutH,
         int M, int N, int K)
{
    extern __shared__ char dsm[];
    const uint32_t sbase = (smem_u32(dsm) + 1023u) & ~1023u;

    const int tid  = threadIdx.x;
    const int lane = tid & 31;
    const int warp = tid >> 5;
    const int wm = warp & 1;
    const int wn = warp >> 1;
    const int m0 = blockIdx.y * 128;
    const int n0 = blockIdx.x * 128;

    const int lr = tid >> 3;
    const int lc = tid & 7;

    const char* pA = (const char*)A2 + (size_t)m0 * K * 2;
    const char* pB = (const char*)B2 + (size_t)n0 * K * 2;

    float acc[4][4][4] = {};
    const int NKI = K / BK;

    auto load_stage = [&](int s, int it) {
        const uint32_t ss = sbase + s * SBYTES;
        const int gko = it * BK * 2;
        #pragma unroll
        for (int i = 0; i < 4; i++) {
            int r = lr + i * 32;
            cp16(swz(ss, r, lc), pA + (size_t)r * K * 2 + gko + lc * 16);
            cp16(swz(ss + 16384, r, lc), pB + (size_t)r * K * 2 + gko + lc * 16);
        }
    };

    auto compute_stage = [&](int s) {
        const uint32_t ss = sbase + s * SBYTES;
        #pragma unroll
        for (int ks = 0; ks < 4; ks++) {
            uint32_t a[4][4];
            #pragma unroll
            for (int mt = 0; mt < 4; mt++) {
                int row = wm * 64 + mt * 16 + (lane & 15);
                int kc  = ks * 2 + (lane >> 4);
                ldsm4(a[mt], swz(ss, row, kc));
            }
            uint32_t b[2][4];
            #pragma unroll
            for (int jj = 0; jj < 2; jj++) {
                int row = wn * 32 + jj * 16 + (lane & 7) + ((lane >> 4) << 3);
                int kc  = ks * 2 + ((lane >> 3) & 1);
                ldsm4(b[jj], swz(ss + 16384, row, kc));
            }
            #pragma unroll
            for (int mt = 0; mt < 4; mt++)
                #pragma unroll
                for (int nt = 0; nt < 4; nt++)
                    mma16816(acc[mt][nt], a[mt], &b[nt >> 1][(nt & 1) * 2]);
        }
    };

    #pragma unroll
    for (int s = 0; s < STAGES - 1; s++) { load_stage(s, s); cpcommit(); }

    for (int it = 0; it < NKI; it++) {
        asm volatile("cp.async.wait_group %0;" :: "n"(STAGES - 2) : "memory");
        __syncthreads();
        const int nit = it + STAGES - 1;
        if (nit < NKI) load_stage(nit % STAGES, nit);
        cpcommit();
        compute_stage(it % STAGES);
    }

    const int rr = lane >> 2;
    const int cc = (lane & 3) * 2;
    #pragma unroll
    for (int mt = 0; mt < 4; mt++)
        #pragma unroll
        for (int nt = 0; nt < 4; nt++) {
            const int col = n0 + wn * 32 + nt * 8 + cc;
            const float b0 = bias[col], b1 = bias[col + 1];
            #pragma unroll
            for (int hf = 0; hf < 2; hf++) {
                const int row = m0 + wm * 64 + mt * 16 + rr + hf * 8;
                float v0 = acc[mt][nt][hf * 2 + 0] + b0;
                float v1 = acc[mt][nt][hf * 2 + 1] + b1;
                if (OUT_HALF) {
                    OutH[((size_t)row * N + col) >> 1] = f16x2_of(v0, v1);
                } else {
                    *(float2*)&OutF[(size_t)row * N + col] = make_float2(v0, v1);
                }
            }
        }
}

// ---------------------------------------------------------------------------
// Flash attention (causal), single-pass fp16, warp M-tile 32, QTILE=256,
// KTILE=128 loaded per stage, processed as 2x 64-col subtiles (same register
// footprint / identical numeric order as R10; half the syncs & loader bursts).
// smem: Q 32K + 2 stages x (K 16K | V 16K) = 97 KB, 1 CTA/SM.
// ---------------------------------------------------------------------------
#define QTILE 256
#define KTILE 128
#define ASTAGE 32768
#define ATTN_DSM (32768 + 2 * ASTAGE + 1024)

__global__ void __launch_bounds__(256, 1)
attn_mma(const uint32_t* __restrict__ qkvf, uint32_t* __restrict__ of)
{
    extern __shared__ char dsm[];
    const uint32_t sb = (smem_u32(dsm) + 1023u) & ~1023u;
    const uint32_t sQ = sb, sStage = sb + 32768;

    const int tid = threadIdx.x;
    const int lane = tid & 31;
    const int wm = tid >> 5;
    const int qt = (int)gridDim.x - 1 - (int)blockIdx.x;   // heavy tiles first
    const int h  = blockIdx.y;
    const int b  = blockIdx.z;
    const int t0 = qt * QTILE;
    const int bT = b * TT;

    const char* pf = (const char*)qkvf;
    const int nkt = 2 * (qt + 1);      // 128-col k-tiles

    auto load_q = [&]() {
        #pragma unroll
        for (int i = 0; i < 8; i++) {
            int idx = i * 256 + tid;
            int r = idx >> 3, c = idx & 7;
            cp16(swz(sQ, r, c), pf + ((size_t)(bT + t0 + r) * C3 + h * HD) * 2 + c * 16);
        }
    };
    // K tile: 128 rows x 64 d at ss; V tile: 128 rows x 64 d at ss+16384
    auto load_kv = [&](int kt, int buf) {
        const uint32_t ss = sStage + buf * ASTAGE;
        const int c = tid & 7;
        #pragma unroll
        for (int i = 0; i < 4; i++) {
            int r = (tid >> 3) + i * 32;
            size_t rowg = (size_t)(bT + kt * KTILE + r) * C3;
            cp16(swz(ss,         r, c), pf + (rowg + CC + h * HD) * 2 + c * 16);
            cp16(swz(ss + 16384, r, c), pf + (rowg + 2 * CC + h * HD) * 2 + c * 16);
        }
    };

    load_q();
    load_kv(0, 0);
    cpcommit();

    uint32_t qf[2][4][4];
    float oacc[2][8][4] = {};
    float m_prev[2][2] = {{-1e30f, -1e30f}, {-1e30f, -1e30f}};
    float l_run[2][2] = {};
    const float scale = 0.125f;
    bool qload = false;

    for (int kt = 0; kt < nkt; kt++) {
        if (kt + 1 < nkt) { load_kv(kt + 1, (kt + 1) & 1); cpcommit(); cpwait1(); }
        else cpwait0();
        __syncthreads();

        if (!qload) {
            qload = true;
            #pragma unroll
            for (int mt = 0; mt < 2; mt++)
                #pragma unroll
                for (int ks = 0; ks < 4; ks++) {
                    int row = wm * 32 + mt * 16 + (lane & 15);
                    int c = ks * 2 + (lane >> 4);
                    ldsm4(qf[mt][ks], swz(sQ, row, c));
                }
        }

        const uint32_t ss = sStage + (kt & 1) * ASTAGE;

        #pragma unroll
        for (int sub = 0; sub < 2; sub++) {
            const int cb = kt * KTILE + sub * 64;        // column base
            const bool doCompute = cb <= (t0 + wm * 32 + 31);
            if (!doCompute) continue;

            // ---- S = Q K^T on 64 cols ----
            float sacc[2][8][4] = {};
            #pragma unroll
            for (int ks = 0; ks < 4; ks++) {
                uint32_t bh[4][4];
                #pragma unroll
                for (int jj = 0; jj < 4; jj++) {
                    int row = sub * 64 + jj * 16 + (lane & 7) + ((lane >> 4) << 3);
                    int c = ks * 2 + ((lane >> 3) & 1);
                    ldsm4(bh[jj], swz(ss, row, c));
                }
                #pragma unroll
                for (int mt = 0; mt < 2; mt++)
                    #pragma unroll
                    for (int nt = 0; nt < 8; nt++)
                        mma16816(sacc[mt][nt], qf[mt][ks], &bh[nt >> 1][(nt & 1) * 2]);
            }

            // ---- scale + causal mask + online softmax (per mt) ----
            #pragma unroll
            for (int mt = 0; mt < 2; mt++) {
                const int rbase = t0 + wm * 32 + mt * 16;
                const bool anyMask = (cb + 63) > rbase;
                #pragma unroll
                for (int nt = 0; nt < 8; nt++)
                    #pragma unroll
                    for (int e = 0; e < 4; e++) {
                        float v = sacc[mt][nt][e] * scale;
                        if (anyMask) {
                            int rg = rbase + (lane >> 2) + (e >> 1) * 8;
                            int cg = cb + nt * 8 + (lane & 3) * 2 + (e & 1);
                            if (cg > rg) v = -1e30f;
                        }
                        sacc[mt][nt][e] = v;
                    }

                #pragma unroll
                for (int rh = 0; rh < 2; rh++) {
                    float mloc = -1e30f;
                    #pragma unroll
                    for (int nt = 0; nt < 8; nt++)
                        mloc = fmaxf(mloc, fmaxf(sacc[mt][nt][rh * 2], sacc[mt][nt][rh * 2 + 1]));
                    mloc = fmaxf(mloc, __shfl_xor_sync(0xffffffffu, mloc, 1));
                    mloc = fmaxf(mloc, __shfl_xor_sync(0xffffffffu, mloc, 2));
                    float mnew = fmaxf(m_prev[mt][rh], mloc);
                    float corr = __expf(m_prev[mt][rh] - mnew);
                    m_prev[mt][rh] = mnew;
                    float ls = 0.0f;
                    #pragma unroll
                    for (int nt = 0; nt < 8; nt++) {
                        float p0 = __expf(sacc[mt][nt][rh * 2]     - mnew);
                        float p1 = __expf(sacc[mt][nt][rh * 2 + 1] - mnew);
                        sacc[mt][nt][rh * 2] = p0; sacc[mt][nt][rh * 2 + 1] = p1;
                        ls += p0 + p1;
                    }
                    ls += __shfl_xor_sync(0xffffffffu, ls, 1);
                    ls += __shfl_xor_sync(0xffffffffu, ls, 2);
                    l_run[mt][rh] = l_run[mt][rh] * corr + ls;
                    #pragma unroll
                    for (int nt = 0; nt < 8; nt++) {
                        oacc[mt][nt][rh * 2]     *= corr;
                        oacc[mt][nt][rh * 2 + 1] *= corr;
                    }
                }
            }

            // ---- O += P V on the same 64 k-rows ----
            #pragma unroll
            for (int jp = 0; jp < 4; jp++) {
                uint32_t vh[4][4];
                #pragma unroll
                for (int jd = 0; jd < 4; jd++) {
                    int row = sub * 64 + jp * 16 + (lane & 7) + (((lane >> 3) & 1) << 3);
                    int c = 2 * jd + (lane >> 4);
                    ldsm4t(vh[jd], swz(ss + 16384, row, c));
                }
                #pragma unroll
                for (int mt = 0; mt < 2; mt++) {
                    uint32_t pa[4];
                    const float* f0 = sacc[mt][2 * jp];
                    const float* f1 = sacc[mt][2 * jp + 1];
                    pa[0] = f16x2_of(f0[0], f0[1]);
                    pa[1] = f16x2_of(f0[2], f0[3]);
                    pa[2] = f16x2_of(f1[0], f1[1]);
                    pa[3] = f16x2_of(f1[2], f1[3]);
                    #pragma unroll
                    for (int nt = 0; nt < 8; nt++)
                        mma16816(oacc[mt][nt], pa, &vh[nt >> 1][(nt & 1) * 2]);
                }
            }
        }
        __syncthreads();
    }

    // ---- epilogue: normalize, fp16, store ----
    #pragma unroll
    for (int mt = 0; mt < 2; mt++)
        #pragma unroll
        for (int rh = 0; rh < 2; rh++) {
            float iv = 1.0f / l_run[mt][rh];
            #pragma unroll
            for (int nt = 0; nt < 8; nt++) {
                float o0 = oacc[mt][nt][rh * 2] * iv;
                float o1 = oacc[mt][nt][rh * 2 + 1] * iv;
                size_t token = (size_t)(bT + t0 + wm * 32 + mt * 16 + (lane >> 2) + rh * 8);
                of[(token * CC + h * HD + nt * 8 + (lane & 3) * 2) >> 1] = f16x2_of(o0, o1);
            }
        }
}

// ---------------------------------------------------------------------------
// Launch
// ---------------------------------------------------------------------------
extern "C" void kernel_launch(void* const* d_in, const int* in_sizes, int n_in,
                              void* d_out, int out_size)
{
    const float* x      = (const float*)d_in[0];
    const float* qkv_w  = (const float*)d_in[1];
    const float* qkv_b  = (const float*)d_in[2];
    const float* out_w  = (const float*)d_in[3];
    const float* out_b  = (const float*)d_in[4];
    float* out = (float*)d_out;

    uint32_t *xf, *w1f, *w2f, *qf, *atf;
    cudaGetSymbolAddress((void**)&xf, g_xf);
    cudaGetSymbolAddress((void**)&w1f, g_w1f);
    cudaGetSymbolAddress((void**)&w2f, g_w2f);
    cudaGetSymbolAddress((void**)&qf, g_qkvf);
    cudaGetSymbolAddress((void**)&atf, g_atf);

    cudaFuncSetAttribute(gemm_mma<true>,  cudaFuncAttributeMaxDynamicSharedMemorySize, GEMM_DSM);
    cudaFuncSetAttribute(gemm_mma<false>, cudaFuncAttributeMaxDynamicSharedMemorySize, GEMM_DSM);
    cudaFuncSetAttribute(attn_mma, cudaFuncAttributeMaxDynamicSharedMemorySize, ATTN_DSM);

    // 0) convert x and weights to fp16
    {
        int n4 = MTOK * CC / 4;
        cvt_f16<<<n4 / 256, 256>>>((const float4*)x, xf, n4);
        n4 = C3 * CC / 4;
        cvt_f16<<<n4 / 256, 256>>>((const float4*)qkv_w, w1f, n4);
        n4 = CC * CC / 4;
        cvt_f16<<<n4 / 256, 256>>>((const float4*)out_w, w2f, n4);
    }
    // 1) QKV projection -> fp16 qkv
    {
        dim3 grid(C3 / 128, MTOK / 128);
        gemm_mma<true><<<grid, 256, GEMM_DSM>>>(xf, w1f, qkv_b, nullptr, qf, MTOK, C3, CC);
    }
    // 2) Causal flash attention -> fp16
    {
        dim3 grid(TT / QTILE, HH, BB);
        attn_mma<<<grid, 256, ATTN_DSM>>>(qf, atf);
    }
    // 3) Output projection -> fp32
    {
        dim3 grid(CC / 128, MTOK / 128);
        gemm_mma<false><<<grid, 256, GEMM_DSM>>>(atf, w2f, out_b, out, nullptr, MTOK, CC, CC);
    }
}